// round 2
// baseline (speedup 1.0000x reference)
#include <cuda_runtime.h>

#define NN 50000
#define EE 800000
#define RR 3
#define FIN 256
#define CC 128
#define BB 4096
#define DTC 0.25f

// ---------------- static scratch (no runtime allocation allowed) ----------------
__device__ __align__(16) float g_P[(size_t)NN * CC];   // phi0 / x ping
__device__ __align__(16) float g_Q[(size_t)NN * CC];   // phi1 / x pong
__device__ int   g_cnt[NN];
__device__ int   g_ptr[NN + 1];
__device__ int   g_cur[NN];
__device__ float g_dinv[NN];
__device__ int   g_srcs[EE];

// ---------------- CSC build: histogram -> scan -> scatter ----------------
__global__ void zero_kernel() {
    int i = blockIdx.x * blockDim.x + threadIdx.x;
    if (i < NN) g_cnt[i] = 0;
}

__global__ void hist_kernel(const int* __restrict__ col) {
    int e = blockIdx.x * blockDim.x + threadIdx.x;
    if (e < EE) atomicAdd(&g_cnt[col[e]], 1);
}

__global__ void __launch_bounds__(1024) scan_kernel() {
    __shared__ int sh[1024];
    int t = threadIdx.x;
    int run = 0;
    const int TILE = 8192;                 // 8 elements per thread per tile
    for (int base = 0; base < NN; base += TILE) {
        int v[8];
        int s = 0;
        int i0 = base + t * 8;
        #pragma unroll
        for (int j = 0; j < 8; j++) {
            int idx = i0 + j;
            v[j] = (idx < NN) ? g_cnt[idx] : 0;
            s += v[j];
        }
        sh[t] = s;
        __syncthreads();
        #pragma unroll
        for (int off = 1; off < 1024; off <<= 1) {
            int add = (t >= off) ? sh[t - off] : 0;
            __syncthreads();
            sh[t] += add;
            __syncthreads();
        }
        int excl = run + sh[t] - s;        // exclusive prefix for this thread's chunk
        int tot  = sh[1023];
        #pragma unroll
        for (int j = 0; j < 8; j++) {
            int idx = i0 + j;
            if (idx < NN) {
                g_ptr[idx] = excl;
                g_cur[idx] = excl;
                g_dinv[idx] = (v[j] > 0) ? (1.0f / sqrtf((float)v[j])) : 0.0f;
            }
            excl += v[j];
        }
        run += tot;
        __syncthreads();
    }
    if (t == 0) g_ptr[NN] = run;
}

__global__ void scatter_kernel(const int* __restrict__ row,
                               const int* __restrict__ col) {
    int e = blockIdx.x * blockDim.x + threadIdx.x;
    if (e < EE) {
        int c = col[e];
        int s = row[e];
        int p = atomicAdd(&g_cur[c], 1);
        g_srcs[p] = s;
    }
}

// ---------------- GEMM: phi = X @ W^T + b  (two weight sets via blockIdx.y) ----------------
// X: [NN, FIN] row-major, W: [CC, FIN] row-major. out[i,j] = sum_k X[i,k]*W[j,k] + b[j]
__global__ void __launch_bounds__(256) gemm_kernel(const float* __restrict__ X,
                                                   const float* __restrict__ W0,
                                                   const float* __restrict__ B0,
                                                   const float* __restrict__ W1,
                                                   const float* __restrict__ B1) {
    const float* W  = blockIdx.y ? W1 : W0;
    const float* Bv = blockIdx.y ? B1 : B0;
    float* out      = blockIdx.y ? g_Q : g_P;

    __shared__ float As[8][128];
    __shared__ float Bs[8][128];

    int tid = threadIdx.x;                 // 256 threads
    int aRow = tid >> 1;                   // 0..127
    int aK   = (tid & 1) << 2;             // 0 or 4
    int rowBase = blockIdx.x * 128;
    int tx = tid & 15, ty = tid >> 4;      // 16 x 16 thread grid, 8x8 per thread

    float acc[8][8];
    #pragma unroll
    for (int m = 0; m < 8; m++)
        #pragma unroll
        for (int n = 0; n < 8; n++) acc[m][n] = 0.0f;

    bool aValid = (rowBase + aRow) < NN;
    const float* Xp = X + (size_t)(rowBase + aRow) * FIN + aK;
    const float* Wp = W + (size_t)aRow * FIN + aK;

    for (int k0 = 0; k0 < FIN; k0 += 8) {
        float4 av = aValid ? *(const float4*)(Xp + k0) : make_float4(0.f, 0.f, 0.f, 0.f);
        float4 bv = *(const float4*)(Wp + k0);
        As[aK + 0][aRow] = av.x; As[aK + 1][aRow] = av.y;
        As[aK + 2][aRow] = av.z; As[aK + 3][aRow] = av.w;
        Bs[aK + 0][aRow] = bv.x; Bs[aK + 1][aRow] = bv.y;
        Bs[aK + 2][aRow] = bv.z; Bs[aK + 3][aRow] = bv.w;
        __syncthreads();
        #pragma unroll
        for (int k = 0; k < 8; k++) {
            float ra[8], rb[8];
            #pragma unroll
            for (int m = 0; m < 8; m++) ra[m] = As[k][ty * 8 + m];
            #pragma unroll
            for (int n = 0; n < 8; n++) rb[n] = Bs[k][tx * 8 + n];
            #pragma unroll
            for (int m = 0; m < 8; m++)
                #pragma unroll
                for (int n = 0; n < 8; n++) acc[m][n] += ra[m] * rb[n];
        }
        __syncthreads();
    }

    #pragma unroll
    for (int m = 0; m < 8; m++) {
        int row = rowBase + ty * 8 + m;
        if (row < NN) {
            #pragma unroll
            for (int n = 0; n < 8; n += 4) {
                int colj = tx * 8 + n;
                float4 v;
                v.x = acc[m][n + 0] + Bv[colj + 0];
                v.y = acc[m][n + 1] + Bv[colj + 1];
                v.z = acc[m][n + 2] + Bv[colj + 2];
                v.w = acc[m][n + 3] + Bv[colj + 3];
                *(float4*)(out + (size_t)row * CC + colj) = v;
            }
        }
    }
}

// ---------------- fused SpMM + wave update ----------------
// out[i,c] = cg * dinv[i] * sum_{s in in(i)} dinv[s]*xg[s,c]  +  ca*xa[i,c]  +  cb*xg[i,c]
// init:  xg=phi0(P), xa=phi1(Q), out=Q, cg=dt^2/2, ca=dt, cb=1
// step:  xg=x_cur,   xa=x_prev,  out=x_prev-buffer, cg=dt^2, ca=-1, cb=2
__global__ void __launch_bounds__(256) spmm_kernel(const float* __restrict__ xg,
                                                   const float* __restrict__ xa,
                                                   float* __restrict__ out,
                                                   float cg, float ca, float cb) {
    int w    = (blockIdx.x * blockDim.x + threadIdx.x) >> 5;  // one warp per dst node
    int lane = threadIdx.x & 31;
    if (w >= NN) return;
    int p0 = g_ptr[w], p1 = g_ptr[w + 1];

    float4 acc = make_float4(0.f, 0.f, 0.f, 0.f);
    #pragma unroll 4
    for (int k = p0; k < p1; k++) {
        int   s  = __ldg(&g_srcs[k]);           // uniform across warp -> broadcast
        float wt = __ldg(&g_dinv[s]);
        float4 xv = *(const float4*)(xg + (size_t)s * CC + lane * 4);
        acc.x += wt * xv.x;
        acc.y += wt * xv.y;
        acc.z += wt * xv.z;
        acc.w += wt * xv.w;
    }
    float di = g_dinv[w];
    float cgd = cg * di;
    size_t o = (size_t)w * CC + lane * 4;
    float4 av = *(const float4*)(xa + o);
    float4 gv = *(const float4*)(xg + o);
    float4 r;
    r.x = cgd * acc.x + ca * av.x + cb * gv.x;
    r.y = cgd * acc.y + ca * av.y + cb * gv.y;
    r.z = cgd * acc.z + ca * av.z + cb * gv.z;
    r.w = cgd * acc.w + ca * av.w + cb * gv.w;
    *(float4*)(out + o) = r;
}

// ---------------- final gather: out[b, r*CC + c] = x[batch_nodes[b], c] ----------------
__global__ void gather_kernel(const float* __restrict__ x,
                              const int* __restrict__ bn,
                              float* __restrict__ out, int r) {
    int t = blockIdx.x * blockDim.x + threadIdx.x;
    if (t >= BB * 32) return;
    int b = t >> 5;
    int q = t & 31;                         // float4 index within the 128 channels
    int node = bn[b];
    ((float4*)out)[(size_t)b * (RR * CC / 4) + r * (CC / 4) + q] =
        ((const float4*)x)[(size_t)node * (CC / 4) + q];
}

// ---------------- driver ----------------
extern "C" void kernel_launch(void* const* d_in, const int* in_sizes, int n_in,
                              void* d_out, int out_size) {
    const float* X  = (const float*)d_in[0];
    const int*   EI = (const int*)d_in[1];     // int32 (JAX x64 disabled -> int64 cast is a no-op)
    const int*   BN = (const int*)d_in[2];
    const float* W0 = (const float*)d_in[3];
    const float* B0 = (const float*)d_in[4];
    const float* W1 = (const float*)d_in[5];
    const float* B1 = (const float*)d_in[6];
    float* out = (float*)d_out;

    float *P, *Q;
    cudaGetSymbolAddress((void**)&P, g_P);
    cudaGetSymbolAddress((void**)&Q, g_Q);

    const int EB = (EE + 255) / 256;        // 3125
    const int ZB = (NN + 255) / 256;        // 196
    const int SB = (NN * 32 + 255) / 256;   // spmm: one warp per node
    const int GB = (NN + 127) / 128;        // gemm row blocks (391)

    const float dt2  = DTC * DTC;           // 0.0625
    const float dt2h = 0.5f * dt2;          // 0.03125

    for (int r = 0; r < RR; r++) {
        const int* rowp = EI + (size_t)r * 2 * EE;   // src
        const int* colp = rowp + EE;                 // dst

        // Build CSC (group edges by destination)
        zero_kernel<<<ZB, 256>>>();
        hist_kernel<<<EB, 256>>>(colp);
        scan_kernel<<<1, 1024>>>();
        scatter_kernel<<<EB, 256>>>(rowp, colp);

        // phi0 -> P, phi1 -> Q
        gemm_kernel<<<dim3(GB, 2), 256>>>(X,
                                          W0 + (size_t)r * CC * FIN, B0 + (size_t)r * CC,
                                          W1 + (size_t)r * CC * FIN, B1 + (size_t)r * CC);

        // x1 = dt*phi1 + (dt^2/2)*Ahat phi0 + phi0      (written into Q, in place over phi1)
        spmm_kernel<<<SB, 256>>>(P, Q, Q, dt2h, DTC, 1.0f);
        // three wave steps: xn = dt^2*Ahat xc + 2 xc - xp   (xn overwrites xp's buffer)
        spmm_kernel<<<SB, 256>>>(Q, P, P, dt2, -1.0f, 2.0f);  // cur=Q(x1), prev=P(phi0) -> P
        spmm_kernel<<<SB, 256>>>(P, Q, Q, dt2, -1.0f, 2.0f);  // cur=P,      prev=Q       -> Q
        spmm_kernel<<<SB, 256>>>(Q, P, P, dt2, -1.0f, 2.0f);  // cur=Q,      prev=P       -> P

        // out[b, r*128 + c] = P[batch_nodes[b], c]
        gather_kernel<<<(BB * 32 + 255) / 256, 256>>>(P, BN, out, r);
    }
}

// round 3
// speedup vs baseline: 1.9074x; 1.9074x over previous
#include <cuda_runtime.h>

#define NN 50000
#define EE 800000
#define RR 3
#define FIN 256
#define CC 128
#define BB 4096
#define DTC 0.25f

#define RN (RR * NN)          // 150000 merged nodes
#define RE (RR * EE)          // 2400000 merged edges

// ---------------- static scratch ----------------
__device__ __align__(16) float g_P[(size_t)RN * CC];   // phi0 / x ping  (per relation slabs)
__device__ __align__(16) float g_Q[(size_t)RN * CC];   // phi1 / x pong
__device__ int   g_cnt[RN];
__device__ int   g_ptr[RN + 1];
__device__ int   g_cur[RN];
__device__ float g_dinv[RN];
__device__ int   g_srcs[RE];            // stores GLOBAL src row (rel*NN + s)
__device__ int   g_bsum[256];           // block sums for scan (147 used)
__device__ int   g_boff[256];

// ---------------- CSC build ----------------
__global__ void zero_kernel() {
    int i = blockIdx.x * blockDim.x + threadIdx.x;
    if (i < RN) g_cnt[i] = 0;
}

__global__ void hist_kernel(const int* __restrict__ EI) {
    int e = blockIdx.x * blockDim.x + threadIdx.x;
    int rel = blockIdx.y;
    if (e < EE) {
        int c = EI[(size_t)rel * 2 * EE + EE + e];
        atomicAdd(&g_cnt[rel * NN + c], 1);
    }
}

// per-block exclusive scan of 1024 elements (g_cnt -> g_ptr partial), block sum out
__global__ void __launch_bounds__(1024) scanA_kernel() {
    __shared__ int sh[1024];
    int t = threadIdx.x;
    int i = blockIdx.x * 1024 + t;
    int v = (i < RN) ? g_cnt[i] : 0;
    sh[t] = v;
    __syncthreads();
    #pragma unroll
    for (int off = 1; off < 1024; off <<= 1) {
        int add = (t >= off) ? sh[t - off] : 0;
        __syncthreads();
        sh[t] += add;
        __syncthreads();
    }
    if (i < RN) g_ptr[i] = sh[t] - v;           // exclusive, block-local
    if (t == 1023) g_bsum[blockIdx.x] = sh[t];
}

__global__ void __launch_bounds__(256) scanB_kernel(int nblocks) {
    __shared__ int sh[256];
    int t = threadIdx.x;
    int v = (t < nblocks) ? g_bsum[t] : 0;
    sh[t] = v;
    __syncthreads();
    #pragma unroll
    for (int off = 1; off < 256; off <<= 1) {
        int add = (t >= off) ? sh[t - off] : 0;
        __syncthreads();
        sh[t] += add;
        __syncthreads();
    }
    if (t < nblocks) g_boff[t] = sh[t] - v;     // exclusive block offsets
}

__global__ void scanC_kernel() {
    int i = blockIdx.x * blockDim.x + threadIdx.x;
    if (i < RN) {
        int p = g_ptr[i] + g_boff[i >> 10];
        g_ptr[i] = p;
        g_cur[i] = p;
        int c = g_cnt[i];
        g_dinv[i] = (c > 0) ? (1.0f / sqrtf((float)c)) : 0.0f;
    }
    if (i == 0) g_ptr[RN] = RE;
}

__global__ void scatter_kernel(const int* __restrict__ EI) {
    int e = blockIdx.x * blockDim.x + threadIdx.x;
    int rel = blockIdx.y;
    if (e < EE) {
        const int* base = EI + (size_t)rel * 2 * EE;
        int s = base[e];
        int c = base[EE + e];
        int p = atomicAdd(&g_cur[rel * NN + c], 1);
        g_srcs[p] = rel * NN + s;               // global src row
    }
}

// ---------------- tf32 MMA GEMM: phi = X @ W^T + b ----------------
// grid: (391, 6): y -> rel = y>>1, which = y&1. Block tile 128(M) x 128(N), K = 256.
// 256 threads = 8 warps as 4(m) x 2(n); warp tile 32x64; mma m16n8k8.

__device__ __forceinline__ unsigned f2tf(float f) {
    unsigned u;
    asm("cvt.rna.tf32.f32 %0, %1;" : "=r"(u) : "f"(f));
    return u;
}

#define SPAD 136   // row stride (floats) for [8][*] k-major smem tiles, conflict-free frags

__global__ void __launch_bounds__(256) gemm_kernel(const float* __restrict__ X,
                                                   const float* __restrict__ W0,
                                                   const float* __restrict__ B0,
                                                   const float* __restrict__ W1,
                                                   const float* __restrict__ B1) {
    int rel   = blockIdx.y >> 1;
    int which = blockIdx.y & 1;
    const float* W  = (which ? W1 : W0) + (size_t)rel * CC * FIN;
    const float* Bv = (which ? B1 : B0) + (size_t)rel * CC;
    float* out      = (which ? g_Q : g_P) + (size_t)rel * NN * CC;

    __shared__ unsigned As[8 * SPAD];   // As[k][m] (tf32 bits)
    __shared__ unsigned Bs[8 * SPAD];   // Bs[k][n]

    int tid  = threadIdx.x;
    int lane = tid & 31;
    int wid  = tid >> 5;
    int gid  = lane >> 2;               // 0..7
    int tig  = lane & 3;                // 0..3
    int m0w  = (wid >> 1) * 32;         // warp m offset (0,32,64,96)
    int n0w  = (wid & 1) * 64;          // warp n offset (0,64)

    int rowBase = blockIdx.x * 128;
    int lrow = tid >> 1;                // 0..127 (load row)
    int lkq  = (tid & 1) * 4;           // 0 or 4

    bool aValid = (rowBase + lrow) < NN;
    const float* Xp = X + (size_t)(rowBase + lrow) * FIN + lkq;
    const float* Wp = W + (size_t)lrow * FIN + lkq;

    float d[2][8][4];
    #pragma unroll
    for (int mt = 0; mt < 2; mt++)
        #pragma unroll
        for (int nt = 0; nt < 8; nt++)
            #pragma unroll
            for (int i = 0; i < 4; i++) d[mt][nt][i] = 0.0f;

    for (int k0 = 0; k0 < FIN; k0 += 8) {
        float4 av = aValid ? *(const float4*)(Xp + k0) : make_float4(0.f, 0.f, 0.f, 0.f);
        float4 bv = *(const float4*)(Wp + k0);
        As[(lkq + 0) * SPAD + lrow] = f2tf(av.x);
        As[(lkq + 1) * SPAD + lrow] = f2tf(av.y);
        As[(lkq + 2) * SPAD + lrow] = f2tf(av.z);
        As[(lkq + 3) * SPAD + lrow] = f2tf(av.w);
        Bs[(lkq + 0) * SPAD + lrow] = f2tf(bv.x);
        Bs[(lkq + 1) * SPAD + lrow] = f2tf(bv.y);
        Bs[(lkq + 2) * SPAD + lrow] = f2tf(bv.z);
        Bs[(lkq + 3) * SPAD + lrow] = f2tf(bv.w);
        __syncthreads();

        unsigned a[2][4];
        #pragma unroll
        for (int mt = 0; mt < 2; mt++) {
            int m0 = m0w + mt * 16;
            a[mt][0] = As[tig * SPAD + m0 + gid];
            a[mt][1] = As[tig * SPAD + m0 + 8 + gid];
            a[mt][2] = As[(tig + 4) * SPAD + m0 + gid];
            a[mt][3] = As[(tig + 4) * SPAD + m0 + 8 + gid];
        }
        #pragma unroll
        for (int nt = 0; nt < 8; nt++) {
            int n0 = n0w + nt * 8;
            unsigned b0 = Bs[tig * SPAD + n0 + gid];
            unsigned b1 = Bs[(tig + 4) * SPAD + n0 + gid];
            #pragma unroll
            for (int mt = 0; mt < 2; mt++) {
                asm volatile(
                    "mma.sync.aligned.m16n8k8.row.col.f32.tf32.tf32.f32 "
                    "{%0,%1,%2,%3}, {%4,%5,%6,%7}, {%8,%9}, {%0,%1,%2,%3};\n"
                    : "+f"(d[mt][nt][0]), "+f"(d[mt][nt][1]),
                      "+f"(d[mt][nt][2]), "+f"(d[mt][nt][3])
                    : "r"(a[mt][0]), "r"(a[mt][1]), "r"(a[mt][2]), "r"(a[mt][3]),
                      "r"(b0), "r"(b1));
            }
        }
        __syncthreads();
    }

    // epilogue: d0,d1 -> row m0+gid, cols (n0+tig*2, +1); d2,d3 -> row m0+8+gid
    #pragma unroll
    for (int mt = 0; mt < 2; mt++) {
        int r0 = rowBase + m0w + mt * 16 + gid;
        int r1 = r0 + 8;
        #pragma unroll
        for (int nt = 0; nt < 8; nt++) {
            int cidx = n0w + nt * 8 + tig * 2;
            float bx = Bv[cidx], by = Bv[cidx + 1];
            if (r0 < NN) {
                float2 v = make_float2(d[mt][nt][0] + bx, d[mt][nt][1] + by);
                *(float2*)(out + (size_t)r0 * CC + cidx) = v;
            }
            if (r1 < NN) {
                float2 v = make_float2(d[mt][nt][2] + bx, d[mt][nt][3] + by);
                *(float2*)(out + (size_t)r1 * CC + cidx) = v;
            }
        }
    }
}

// ---------------- fused SpMM + wave update (merged over relations) ----------------
// out[i,c] = cg*dinv[i]*sum_{s in in(i)} dinv[s]*xg[s,c] + ca*xa[i,c] + cb*xg[i,c]
__global__ void __launch_bounds__(256) spmm_kernel(const float* __restrict__ xg,
                                                   const float* __restrict__ xa,
                                                   float* __restrict__ out,
                                                   float cg, float ca, float cb) {
    int w    = (blockIdx.x * blockDim.x + threadIdx.x) >> 5;  // global dst row
    int lane = threadIdx.x & 31;
    if (w >= RN) return;
    int p0 = g_ptr[w], p1 = g_ptr[w + 1];

    float4 acc = make_float4(0.f, 0.f, 0.f, 0.f);
    #pragma unroll 4
    for (int k = p0; k < p1; k++) {
        int   s  = __ldg(&g_srcs[k]);           // global src row (uniform -> broadcast)
        float wt = __ldg(&g_dinv[s]);
        float4 xv = *(const float4*)(xg + (size_t)s * CC + lane * 4);
        acc.x += wt * xv.x;
        acc.y += wt * xv.y;
        acc.z += wt * xv.z;
        acc.w += wt * xv.w;
    }
    float cgd = cg * g_dinv[w];
    size_t o = (size_t)w * CC + lane * 4;
    float4 av = *(const float4*)(xa + o);
    float4 gv = *(const float4*)(xg + o);
    float4 r;
    r.x = cgd * acc.x + ca * av.x + cb * gv.x;
    r.y = cgd * acc.y + ca * av.y + cb * gv.y;
    r.z = cgd * acc.z + ca * av.z + cb * gv.z;
    r.w = cgd * acc.w + ca * av.w + cb * gv.w;
    *(float4*)(out + o) = r;
}

// ---------------- final gather: out[b, r*CC + c] = x[r*NN + bn[b], c] ----------------
__global__ void gather_kernel(const float* __restrict__ x,
                              const int* __restrict__ bn,
                              float* __restrict__ out) {
    int t = blockIdx.x * blockDim.x + threadIdx.x;
    if (t >= BB * RR * 32) return;
    int q = t & 31;
    int r = (t >> 5) % RR;
    int b = t / (32 * RR);
    int node = bn[b];
    ((float4*)out)[(size_t)b * (RR * CC / 4) + r * (CC / 4) + q] =
        ((const float4*)x)[((size_t)r * NN + node) * (CC / 4) + q];
}

// ---------------- driver ----------------
extern "C" void kernel_launch(void* const* d_in, const int* in_sizes, int n_in,
                              void* d_out, int out_size) {
    const float* X  = (const float*)d_in[0];
    const int*   EI = (const int*)d_in[1];
    const int*   BN = (const int*)d_in[2];
    const float* W0 = (const float*)d_in[3];
    const float* B0 = (const float*)d_in[4];
    const float* W1 = (const float*)d_in[5];
    const float* B1 = (const float*)d_in[6];
    float* out = (float*)d_out;

    float *P, *Q;
    cudaGetSymbolAddress((void**)&P, g_P);
    cudaGetSymbolAddress((void**)&Q, g_Q);

    const int EB = (EE + 255) / 256;          // 3125
    const int ZB = (RN + 255) / 256;          // 586
    const int SCB = (RN + 1023) / 1024;       // 147 scan blocks
    const int SB = (RN * 32 + 255) / 256;     // spmm: one warp per node
    const int GB = (NN + 127) / 128;          // 391 gemm row blocks

    const float dt2  = DTC * DTC;             // 0.0625
    const float dt2h = 0.5f * dt2;            // 0.03125

    // CSC build, all relations at once
    zero_kernel<<<ZB, 256>>>();
    hist_kernel<<<dim3(EB, RR), 256>>>(EI);
    scanA_kernel<<<SCB, 1024>>>();
    scanB_kernel<<<1, 256>>>(SCB);
    scanC_kernel<<<ZB, 256>>>();
    scatter_kernel<<<dim3(EB, RR), 256>>>(EI);

    // phi0 -> P slabs, phi1 -> Q slabs (6 GEMMs in one launch)
    gemm_kernel<<<dim3(GB, 2 * RR), 256>>>(X, W0, B0, W1, B1);

    // x1 = dt*phi1 + (dt^2/2)*Ahat phi0 + phi0
    spmm_kernel<<<SB, 256>>>(P, Q, Q, dt2h, DTC, 1.0f);
    // three wave steps: xn = dt^2*Ahat xc + 2 xc - xp
    spmm_kernel<<<SB, 256>>>(Q, P, P, dt2, -1.0f, 2.0f);
    spmm_kernel<<<SB, 256>>>(P, Q, Q, dt2, -1.0f, 2.0f);
    spmm_kernel<<<SB, 256>>>(Q, P, P, dt2, -1.0f, 2.0f);

    gather_kernel<<<(BB * RR * 32 + 255) / 256, 256>>>(P, BN, out);
}

// round 4
// speedup vs baseline: 1.9774x; 1.0367x over previous
#include <cuda_runtime.h>
#include <cuda_fp16.h>

#define NN 50000
#define EE 800000
#define RR 3
#define FIN 256
#define CC 128
#define BB 4096
#define DTC 0.25f

#define RN (RR * NN)          // 150000 merged nodes
#define RE (RR * EE)          // 2400000 merged edges

// ---------------- static scratch ----------------
__device__ __align__(16) float  g_P[(size_t)RN * CC];   // ping (fp32)
__device__ __align__(16) float  g_Q[(size_t)RN * CC];   // pong (fp32)
__device__ __align__(16) __half g_Ph[(size_t)RN * CC];  // fp16 shadow of P
__device__ __align__(16) __half g_Qh[(size_t)RN * CC];  // fp16 shadow of Q
__device__ int   g_cnt[RN];
__device__ int   g_ptr[RN + 1];
__device__ int   g_cur[RN];
__device__ float g_dinv[RN];
__device__ int   g_srcs[RE];            // GLOBAL src row (rel*NN + s)
__device__ int   g_bsum[256];
__device__ int   g_boff[256];

// ---------------- CSC build ----------------
__global__ void zero_kernel() {
    int i = blockIdx.x * blockDim.x + threadIdx.x;
    if (i < RN) g_cnt[i] = 0;
}

__global__ void hist_kernel(const int* __restrict__ EI) {
    int e = blockIdx.x * blockDim.x + threadIdx.x;
    int rel = blockIdx.y;
    if (e < EE) {
        int c = EI[(size_t)rel * 2 * EE + EE + e];
        atomicAdd(&g_cnt[rel * NN + c], 1);
    }
}

__global__ void __launch_bounds__(1024) scanA_kernel() {
    __shared__ int sh[1024];
    int t = threadIdx.x;
    int i = blockIdx.x * 1024 + t;
    int v = (i < RN) ? g_cnt[i] : 0;
    sh[t] = v;
    __syncthreads();
    #pragma unroll
    for (int off = 1; off < 1024; off <<= 1) {
        int add = (t >= off) ? sh[t - off] : 0;
        __syncthreads();
        sh[t] += add;
        __syncthreads();
    }
    if (i < RN) g_ptr[i] = sh[t] - v;
    if (t == 1023) g_bsum[blockIdx.x] = sh[t];
}

__global__ void __launch_bounds__(256) scanB_kernel(int nblocks) {
    __shared__ int sh[256];
    int t = threadIdx.x;
    int v = (t < nblocks) ? g_bsum[t] : 0;
    sh[t] = v;
    __syncthreads();
    #pragma unroll
    for (int off = 1; off < 256; off <<= 1) {
        int add = (t >= off) ? sh[t - off] : 0;
        __syncthreads();
        sh[t] += add;
        __syncthreads();
    }
    if (t < nblocks) g_boff[t] = sh[t] - v;
}

__global__ void scanC_kernel() {
    int i = blockIdx.x * blockDim.x + threadIdx.x;
    if (i < RN) {
        int p = g_ptr[i] + g_boff[i >> 10];
        g_ptr[i] = p;
        g_cur[i] = p;
        int c = g_cnt[i];
        g_dinv[i] = (c > 0) ? (1.0f / sqrtf((float)c)) : 0.0f;
    }
    if (i == 0) g_ptr[RN] = RE;
}

__global__ void scatter_kernel(const int* __restrict__ EI) {
    int e = blockIdx.x * blockDim.x + threadIdx.x;
    int rel = blockIdx.y;
    if (e < EE) {
        const int* base = EI + (size_t)rel * 2 * EE;
        int s = base[e];
        int c = base[EE + e];
        int p = atomicAdd(&g_cur[rel * NN + c], 1);
        g_srcs[p] = rel * NN + s;
    }
}

// ---------------- tf32 MMA GEMM (double-buffered): phi = X @ W^T + b ----------------
__device__ __forceinline__ unsigned f2tf(float f) {
    unsigned u;
    asm("cvt.rna.tf32.f32 %0, %1;" : "=r"(u) : "f"(f));
    return u;
}

#define SPAD 136

__global__ void __launch_bounds__(256) gemm_kernel(const float* __restrict__ X,
                                                   const float* __restrict__ W0,
                                                   const float* __restrict__ B0,
                                                   const float* __restrict__ W1,
                                                   const float* __restrict__ B1) {
    int rel   = blockIdx.y >> 1;
    int which = blockIdx.y & 1;
    const float* W  = (which ? W1 : W0) + (size_t)rel * CC * FIN;
    const float* Bv = (which ? B1 : B0) + (size_t)rel * CC;
    float*  out  = (which ? g_Q : g_P) + (size_t)rel * NN * CC;
    __half* outh = which ? nullptr : (g_Ph + (size_t)rel * NN * CC);  // phi0 needs fp16 shadow

    __shared__ unsigned As[2][8 * SPAD];
    __shared__ unsigned Bs[2][8 * SPAD];

    int tid  = threadIdx.x;
    int lane = tid & 31;
    int wid  = tid >> 5;
    int gid  = lane >> 2;
    int tig  = lane & 3;
    int m0w  = (wid >> 1) * 32;
    int n0w  = (wid & 1) * 64;

    int rowBase = blockIdx.x * 128;
    int lrow = tid >> 1;
    int lkq  = (tid & 1) * 4;

    bool aValid = (rowBase + lrow) < NN;
    const float* Xp = X + (size_t)(rowBase + lrow) * FIN + lkq;
    const float* Wp = W + (size_t)lrow * FIN + lkq;

    float d[2][8][4];
    #pragma unroll
    for (int mt = 0; mt < 2; mt++)
        #pragma unroll
        for (int nt = 0; nt < 8; nt++)
            #pragma unroll
            for (int i = 0; i < 4; i++) d[mt][nt][i] = 0.0f;

    // preload k-chunk 0
    float4 av = aValid ? *(const float4*)(Xp) : make_float4(0.f, 0.f, 0.f, 0.f);
    float4 bv = *(const float4*)(Wp);
    As[0][(lkq + 0) * SPAD + lrow] = f2tf(av.x);
    As[0][(lkq + 1) * SPAD + lrow] = f2tf(av.y);
    As[0][(lkq + 2) * SPAD + lrow] = f2tf(av.z);
    As[0][(lkq + 3) * SPAD + lrow] = f2tf(av.w);
    Bs[0][(lkq + 0) * SPAD + lrow] = f2tf(bv.x);
    Bs[0][(lkq + 1) * SPAD + lrow] = f2tf(bv.y);
    Bs[0][(lkq + 2) * SPAD + lrow] = f2tf(bv.z);
    Bs[0][(lkq + 3) * SPAD + lrow] = f2tf(bv.w);
    __syncthreads();

    int buf = 0;
    for (int k0 = 0; k0 < FIN; k0 += 8) {
        bool more = (k0 + 8) < FIN;
        if (more) {
            av = aValid ? *(const float4*)(Xp + k0 + 8) : make_float4(0.f, 0.f, 0.f, 0.f);
            bv = *(const float4*)(Wp + k0 + 8);
        }

        unsigned a[2][4];
        #pragma unroll
        for (int mt = 0; mt < 2; mt++) {
            int m0 = m0w + mt * 16;
            a[mt][0] = As[buf][tig * SPAD + m0 + gid];
            a[mt][1] = As[buf][tig * SPAD + m0 + 8 + gid];
            a[mt][2] = As[buf][(tig + 4) * SPAD + m0 + gid];
            a[mt][3] = As[buf][(tig + 4) * SPAD + m0 + 8 + gid];
        }
        #pragma unroll
        for (int nt = 0; nt < 8; nt++) {
            int n0 = n0w + nt * 8;
            unsigned b0 = Bs[buf][tig * SPAD + n0 + gid];
            unsigned b1 = Bs[buf][(tig + 4) * SPAD + n0 + gid];
            #pragma unroll
            for (int mt = 0; mt < 2; mt++) {
                asm volatile(
                    "mma.sync.aligned.m16n8k8.row.col.f32.tf32.tf32.f32 "
                    "{%0,%1,%2,%3}, {%4,%5,%6,%7}, {%8,%9}, {%0,%1,%2,%3};\n"
                    : "+f"(d[mt][nt][0]), "+f"(d[mt][nt][1]),
                      "+f"(d[mt][nt][2]), "+f"(d[mt][nt][3])
                    : "r"(a[mt][0]), "r"(a[mt][1]), "r"(a[mt][2]), "r"(a[mt][3]),
                      "r"(b0), "r"(b1));
            }
        }

        if (more) {
            int nb = buf ^ 1;
            As[nb][(lkq + 0) * SPAD + lrow] = f2tf(av.x);
            As[nb][(lkq + 1) * SPAD + lrow] = f2tf(av.y);
            As[nb][(lkq + 2) * SPAD + lrow] = f2tf(av.z);
            As[nb][(lkq + 3) * SPAD + lrow] = f2tf(av.w);
            Bs[nb][(lkq + 0) * SPAD + lrow] = f2tf(bv.x);
            Bs[nb][(lkq + 1) * SPAD + lrow] = f2tf(bv.y);
            Bs[nb][(lkq + 2) * SPAD + lrow] = f2tf(bv.z);
            Bs[nb][(lkq + 3) * SPAD + lrow] = f2tf(bv.w);
            __syncthreads();
            buf = nb;
        }
    }

    #pragma unroll
    for (int mt = 0; mt < 2; mt++) {
        int r0 = rowBase + m0w + mt * 16 + gid;
        int r1 = r0 + 8;
        #pragma unroll
        for (int nt = 0; nt < 8; nt++) {
            int cidx = n0w + nt * 8 + tig * 2;
            float bx = Bv[cidx], by = Bv[cidx + 1];
            if (r0 < NN) {
                float2 v = make_float2(d[mt][nt][0] + bx, d[mt][nt][1] + by);
                *(float2*)(out + (size_t)r0 * CC + cidx) = v;
                if (outh) *(__half2*)(outh + (size_t)r0 * CC + cidx) = __floats2half2_rn(v.x, v.y);
            }
            if (r1 < NN) {
                float2 v = make_float2(d[mt][nt][2] + bx, d[mt][nt][3] + by);
                *(float2*)(out + (size_t)r1 * CC + cidx) = v;
                if (outh) *(__half2*)(outh + (size_t)r1 * CC + cidx) = __floats2half2_rn(v.x, v.y);
            }
        }
    }
}

// ---------------- fused SpMM + wave update (fp16 neighbor gather) ----------------
// out[i,c] = cg*dinv[i]*sum_s dinv[s]*xgh[s,c] + ca*xa[i,c] + cb*xg[i,c]
__global__ void __launch_bounds__(256) spmm_kernel(const __half* __restrict__ xgh,
                                                   const float*  __restrict__ xg,
                                                   const float*  __restrict__ xa,
                                                   float*  __restrict__ out,
                                                   __half* __restrict__ outh,
                                                   float cg, float ca, float cb) {
    int w    = (blockIdx.x * blockDim.x + threadIdx.x) >> 5;  // global dst row
    int lane = threadIdx.x & 31;
    if (w >= RN) return;
    int p0 = g_ptr[w], p1 = g_ptr[w + 1];

    float4 acc = make_float4(0.f, 0.f, 0.f, 0.f);
    #pragma unroll 4
    for (int k = p0; k < p1; k++) {
        int   s  = __ldg(&g_srcs[k]);           // uniform across warp -> broadcast
        float wt = __ldg(&g_dinv[s]);
        uint2 hv = *(const uint2*)(xgh + (size_t)s * CC + lane * 4);
        float2 f0 = __half22float2(*(__half2*)&hv.x);
        float2 f1 = __half22float2(*(__half2*)&hv.y);
        acc.x += wt * f0.x;
        acc.y += wt * f0.y;
        acc.z += wt * f1.x;
        acc.w += wt * f1.y;
    }
    float cgd = cg * g_dinv[w];
    size_t o = (size_t)w * CC + lane * 4;
    float4 av = *(const float4*)(xa + o);
    float4 gv = *(const float4*)(xg + o);
    float4 r;
    r.x = cgd * acc.x + ca * av.x + cb * gv.x;
    r.y = cgd * acc.y + ca * av.y + cb * gv.y;
    r.z = cgd * acc.z + ca * av.z + cb * gv.z;
    r.w = cgd * acc.w + ca * av.w + cb * gv.w;
    *(float4*)(out + o) = r;
    if (outh) {
        uint2 hv;
        *(__half2*)&hv.x = __floats2half2_rn(r.x, r.y);
        *(__half2*)&hv.y = __floats2half2_rn(r.z, r.w);
        *(uint2*)(outh + o) = hv;
    }
}

// ---------------- final gather ----------------
__global__ void gather_kernel(const float* __restrict__ x,
                              const int* __restrict__ bn,
                              float* __restrict__ out) {
    int t = blockIdx.x * blockDim.x + threadIdx.x;
    if (t >= BB * RR * 32) return;
    int q = t & 31;
    int r = (t >> 5) % RR;
    int b = t / (32 * RR);
    int node = bn[b];
    ((float4*)out)[(size_t)b * (RR * CC / 4) + r * (CC / 4) + q] =
        ((const float4*)x)[((size_t)r * NN + node) * (CC / 4) + q];
}

// ---------------- driver ----------------
extern "C" void kernel_launch(void* const* d_in, const int* in_sizes, int n_in,
                              void* d_out, int out_size) {
    const float* X  = (const float*)d_in[0];
    const int*   EI = (const int*)d_in[1];
    const int*   BN = (const int*)d_in[2];
    const float* W0 = (const float*)d_in[3];
    const float* B0 = (const float*)d_in[4];
    const float* W1 = (const float*)d_in[5];
    const float* B1 = (const float*)d_in[6];
    float* out = (float*)d_out;

    float *P, *Q;
    __half *Ph, *Qh;
    cudaGetSymbolAddress((void**)&P, g_P);
    cudaGetSymbolAddress((void**)&Q, g_Q);
    cudaGetSymbolAddress((void**)&Ph, g_Ph);
    cudaGetSymbolAddress((void**)&Qh, g_Qh);

    const int EB  = (EE + 255) / 256;
    const int ZB  = (RN + 255) / 256;
    const int SCB = (RN + 1023) / 1024;
    const int SB  = (RN * 32 + 255) / 256;
    const int GB  = (NN + 127) / 128;

    const float dt2  = DTC * DTC;
    const float dt2h = 0.5f * dt2;

    // CSC build (all relations)
    zero_kernel<<<ZB, 256>>>();
    hist_kernel<<<dim3(EB, RR), 256>>>(EI);
    scanA_kernel<<<SCB, 1024>>>();
    scanB_kernel<<<1, 256>>>(SCB);
    scanC_kernel<<<ZB, 256>>>();
    scatter_kernel<<<dim3(EB, RR), 256>>>(EI);

    // phi0 -> P (+Ph), phi1 -> Q
    gemm_kernel<<<dim3(GB, 2 * RR), 256>>>(X, W0, B0, W1, B1);

    // x1 = dt*phi1 + (dt^2/2)*Ahat phi0 + phi0
    spmm_kernel<<<SB, 256>>>(Ph, P, Q, Q, Qh, dt2h, DTC, 1.0f);
    // xn = dt^2*Ahat xc + 2 xc - xp
    spmm_kernel<<<SB, 256>>>(Qh, Q, P, P, Ph, dt2, -1.0f, 2.0f);
    spmm_kernel<<<SB, 256>>>(Ph, P, Q, Q, Qh, dt2, -1.0f, 2.0f);
    spmm_kernel<<<SB, 256>>>(Qh, Q, P, P, nullptr, dt2, -1.0f, 2.0f);

    gather_kernel<<<(BB * RR * 32 + 255) / 256, 256>>>(P, BN, out);
}

// round 8
// speedup vs baseline: 1.9941x; 1.0085x over previous
#include <cuda_runtime.h>
#include <cuda_fp16.h>

#define NN 50000
#define EE 800000
#define RR 3
#define FIN 256
#define CC 128
#define BB 4096
#define DTC 0.25f

#define RN (RR * NN)          // 150000 merged nodes
#define RE (RR * EE)          // 2400000 merged edges

// ---------------- static scratch ----------------
__device__ __align__(16) float  g_P[(size_t)RN * CC];   // ping (fp32)
__device__ __align__(16) float  g_Q[(size_t)RN * CC];   // pong (fp32)
__device__ __align__(16) __half g_Ph[(size_t)RN * CC];  // fp16 shadow of P
__device__ __align__(16) __half g_Qh[(size_t)RN * CC];  // fp16 shadow of Q
__device__ int   g_cnt[RN];
__device__ int   g_ptr[RN + 1];
__device__ int   g_cur[RN];
__device__ float g_dinv[RN];
__device__ __align__(8) int2 g_edge[RE];  // {global src row, bitcast fp32 dinv[src]}
__device__ int   g_bsum[256];
__device__ int   g_boff[256];

// ---------------- CSC build ----------------
__global__ void zero_kernel() {
    int i = blockIdx.x * blockDim.x + threadIdx.x;
    if (i < RN) g_cnt[i] = 0;
}

__global__ void hist_kernel(const int* __restrict__ EI) {
    int e = blockIdx.x * blockDim.x + threadIdx.x;
    int rel = blockIdx.y;
    if (e < EE) {
        int c = EI[(size_t)rel * 2 * EE + EE + e];
        atomicAdd(&g_cnt[rel * NN + c], 1);
    }
}

__global__ void __launch_bounds__(1024) scanA_kernel() {
    __shared__ int sh[1024];
    int t = threadIdx.x;
    int i = blockIdx.x * 1024 + t;
    int v = (i < RN) ? g_cnt[i] : 0;
    sh[t] = v;
    __syncthreads();
    #pragma unroll
    for (int off = 1; off < 1024; off <<= 1) {
        int add = (t >= off) ? sh[t - off] : 0;
        __syncthreads();
        sh[t] += add;
        __syncthreads();
    }
    if (i < RN) g_ptr[i] = sh[t] - v;
    if (t == 1023) g_bsum[blockIdx.x] = sh[t];
}

__global__ void __launch_bounds__(256) scanB_kernel(int nblocks) {
    __shared__ int sh[256];
    int t = threadIdx.x;
    int v = (t < nblocks) ? g_bsum[t] : 0;
    sh[t] = v;
    __syncthreads();
    #pragma unroll
    for (int off = 1; off < 256; off <<= 1) {
        int add = (t >= off) ? sh[t - off] : 0;
        __syncthreads();
        sh[t] += add;
        __syncthreads();
    }
    if (t < nblocks) g_boff[t] = sh[t] - v;
}

__global__ void scanC_kernel() {
    int i = blockIdx.x * blockDim.x + threadIdx.x;
    if (i < RN) {
        int p = g_ptr[i] + g_boff[i >> 10];
        g_ptr[i] = p;
        g_cur[i] = p;
        int c = g_cnt[i];
        g_dinv[i] = (c > 0) ? (1.0f / sqrtf((float)c)) : 0.0f;
    }
    if (i == 0) g_ptr[RN] = RE;
}

__global__ void scatter_kernel(const int* __restrict__ EI) {
    int e = blockIdx.x * blockDim.x + threadIdx.x;
    int rel = blockIdx.y;
    if (e < EE) {
        const int* base = EI + (size_t)rel * 2 * EE;
        int s = rel * NN + base[e];
        int c = base[EE + e];
        int p = atomicAdd(&g_cur[rel * NN + c], 1);
        g_edge[p] = make_int2(s, __float_as_int(g_dinv[s]));
    }
}

// ---------------- tf32 MMA GEMM (double-buffered): phi = X @ W^T + b ----------------
__device__ __forceinline__ unsigned f2tf(float f) {
    unsigned u;
    asm("cvt.rna.tf32.f32 %0, %1;" : "=r"(u) : "f"(f));
    return u;
}

#define SPAD 136

__global__ void __launch_bounds__(256) gemm_kernel(const float* __restrict__ X,
                                                   const float* __restrict__ W0,
                                                   const float* __restrict__ B0,
                                                   const float* __restrict__ W1,
                                                   const float* __restrict__ B1) {
    int rel   = blockIdx.y >> 1;
    int which = blockIdx.y & 1;
    const float* W  = (which ? W1 : W0) + (size_t)rel * CC * FIN;
    const float* Bv = (which ? B1 : B0) + (size_t)rel * CC;
    float* out = (which ? g_Q : g_P) + (size_t)rel * NN * CC;

    __shared__ unsigned As[2][8 * SPAD];
    __shared__ unsigned Bs[2][8 * SPAD];

    int tid  = threadIdx.x;
    int lane = tid & 31;
    int wid  = tid >> 5;
    int gid  = lane >> 2;
    int tig  = lane & 3;
    int m0w  = (wid >> 1) * 32;
    int n0w  = (wid & 1) * 64;

    int rowBase = blockIdx.x * 128;
    int lrow = tid >> 1;
    int lkq  = (tid & 1) * 4;

    bool aValid = (rowBase + lrow) < NN;
    const float* Xp = X + (size_t)(rowBase + lrow) * FIN + lkq;
    const float* Wp = W + (size_t)lrow * FIN + lkq;

    float d[2][8][4];
    #pragma unroll
    for (int mt = 0; mt < 2; mt++)
        #pragma unroll
        for (int nt = 0; nt < 8; nt++)
            #pragma unroll
            for (int i = 0; i < 4; i++) d[mt][nt][i] = 0.0f;

    float4 av = aValid ? *(const float4*)(Xp) : make_float4(0.f, 0.f, 0.f, 0.f);
    float4 bv = *(const float4*)(Wp);
    As[0][(lkq + 0) * SPAD + lrow] = f2tf(av.x);
    As[0][(lkq + 1) * SPAD + lrow] = f2tf(av.y);
    As[0][(lkq + 2) * SPAD + lrow] = f2tf(av.z);
    As[0][(lkq + 3) * SPAD + lrow] = f2tf(av.w);
    Bs[0][(lkq + 0) * SPAD + lrow] = f2tf(bv.x);
    Bs[0][(lkq + 1) * SPAD + lrow] = f2tf(bv.y);
    Bs[0][(lkq + 2) * SPAD + lrow] = f2tf(bv.z);
    Bs[0][(lkq + 3) * SPAD + lrow] = f2tf(bv.w);
    __syncthreads();

    int buf = 0;
    for (int k0 = 0; k0 < FIN; k0 += 8) {
        bool more = (k0 + 8) < FIN;
        if (more) {
            av = aValid ? *(const float4*)(Xp + k0 + 8) : make_float4(0.f, 0.f, 0.f, 0.f);
            bv = *(const float4*)(Wp + k0 + 8);
        }

        unsigned a[2][4];
        #pragma unroll
        for (int mt = 0; mt < 2; mt++) {
            int m0 = m0w + mt * 16;
            a[mt][0] = As[buf][tig * SPAD + m0 + gid];
            a[mt][1] = As[buf][tig * SPAD + m0 + 8 + gid];
            a[mt][2] = As[buf][(tig + 4) * SPAD + m0 + gid];
            a[mt][3] = As[buf][(tig + 4) * SPAD + m0 + 8 + gid];
        }
        #pragma unroll
        for (int nt = 0; nt < 8; nt++) {
            int n0 = n0w + nt * 8;
            unsigned b0 = Bs[buf][tig * SPAD + n0 + gid];
            unsigned b1 = Bs[buf][(tig + 4) * SPAD + n0 + gid];
            #pragma unroll
            for (int mt = 0; mt < 2; mt++) {
                asm volatile(
                    "mma.sync.aligned.m16n8k8.row.col.f32.tf32.tf32.f32 "
                    "{%0,%1,%2,%3}, {%4,%5,%6,%7}, {%8,%9}, {%0,%1,%2,%3};\n"
                    : "+f"(d[mt][nt][0]), "+f"(d[mt][nt][1]),
                      "+f"(d[mt][nt][2]), "+f"(d[mt][nt][3])
                    : "r"(a[mt][0]), "r"(a[mt][1]), "r"(a[mt][2]), "r"(a[mt][3]),
                      "r"(b0), "r"(b1));
            }
        }

        if (more) {
            int nb = buf ^ 1;
            As[nb][(lkq + 0) * SPAD + lrow] = f2tf(av.x);
            As[nb][(lkq + 1) * SPAD + lrow] = f2tf(av.y);
            As[nb][(lkq + 2) * SPAD + lrow] = f2tf(av.z);
            As[nb][(lkq + 3) * SPAD + lrow] = f2tf(av.w);
            Bs[nb][(lkq + 0) * SPAD + lrow] = f2tf(bv.x);
            Bs[nb][(lkq + 1) * SPAD + lrow] = f2tf(bv.y);
            Bs[nb][(lkq + 2) * SPAD + lrow] = f2tf(bv.z);
            Bs[nb][(lkq + 3) * SPAD + lrow] = f2tf(bv.w);
            __syncthreads();
            buf = nb;
        }
    }

    #pragma unroll
    for (int mt = 0; mt < 2; mt++) {
        int r0 = rowBase + m0w + mt * 16 + gid;
        int r1 = r0 + 8;
        #pragma unroll
        for (int nt = 0; nt < 8; nt++) {
            int cidx = n0w + nt * 8 + tig * 2;
            float bx = Bv[cidx], by = Bv[cidx + 1];
            if (r0 < NN)
                *(float2*)(out + (size_t)r0 * CC + cidx) =
                    make_float2(d[mt][nt][0] + bx, d[mt][nt][1] + by);
            if (r1 < NN)
                *(float2*)(out + (size_t)r1 * CC + cidx) =
                    make_float2(d[mt][nt][2] + bx, d[mt][nt][3] + by);
        }
    }
}

// ---------------- coalesced fp32 -> fp16 shadow convert (P -> Ph) ----------------
__global__ void p2h_kernel() {
    size_t i = (size_t)blockIdx.x * blockDim.x + threadIdx.x;
    if (i >= (size_t)RN * CC / 8) return;
    const float4* src = (const float4*)g_P;
    float4 a = src[i * 2];
    float4 b = src[i * 2 + 1];
    uint4 h;
    *(__half2*)&h.x = __floats2half2_rn(a.x, a.y);
    *(__half2*)&h.y = __floats2half2_rn(a.z, a.w);
    *(__half2*)&h.z = __floats2half2_rn(b.x, b.y);
    *(__half2*)&h.w = __floats2half2_rn(b.z, b.w);
    ((uint4*)g_Ph)[i] = h;
}

// ---------------- fused SpMM + wave update (2 edges/warp, fp16 gather) ----------------
// out[i,c] = cg*dinv[i]*sum_s dinv[s]*xgh[s,c] + ca*xa[i,c] + cb*xg[i,c]
__global__ void __launch_bounds__(256) spmm_kernel(const __half* __restrict__ xgh,
                                                   const float*  __restrict__ xg,
                                                   const float*  __restrict__ xa,
                                                   float*  __restrict__ out,
                                                   __half* __restrict__ outh,
                                                   float cg, float ca, float cb) {
    int w    = (blockIdx.x * blockDim.x + threadIdx.x) >> 5;  // global dst row
    int lane = threadIdx.x & 31;
    if (w >= RN) return;
    int p0 = g_ptr[w], p1 = g_ptr[w + 1];
    int half = lane >> 4;                 // which edge of the pair
    int hl   = lane & 15;                 // 16 lanes x 8 fp16 channels

    float acc[8];
    #pragma unroll
    for (int i = 0; i < 8; i++) acc[i] = 0.0f;

    #pragma unroll 2
    for (int k = p0 + half; k < p1; k += 2) {
        int2 e = __ldg(&g_edge[k]);
        float wt = __int_as_float(e.y);
        uint4 hv = *(const uint4*)(xgh + (size_t)e.x * CC + hl * 8);
        float2 f;
        f = __half22float2(*(__half2*)&hv.x); acc[0] += wt * f.x; acc[1] += wt * f.y;
        f = __half22float2(*(__half2*)&hv.y); acc[2] += wt * f.x; acc[3] += wt * f.y;
        f = __half22float2(*(__half2*)&hv.z); acc[4] += wt * f.x; acc[5] += wt * f.y;
        f = __half22float2(*(__half2*)&hv.w); acc[6] += wt * f.x; acc[7] += wt * f.y;
    }
    // combine the two edge-halves: lanes 0-15 end with full sums for chans hl*8..hl*8+7
    #pragma unroll
    for (int i = 0; i < 8; i++) acc[i] += __shfl_down_sync(0xffffffffu, acc[i], 16);
    // redistribute so lane m holds channels m*4..m*4+3 (coalesced fp32 epilogue)
    float v[4];
    #pragma unroll
    for (int j = 0; j < 4; j++) {
        float t0 = __shfl_sync(0xffffffffu, acc[j],     lane >> 1);
        float t1 = __shfl_sync(0xffffffffu, acc[4 + j], lane >> 1);
        v[j] = (lane & 1) ? t1 : t0;
    }

    float cgd = cg * g_dinv[w];
    size_t o = (size_t)w * CC + lane * 4;
    float4 av = *(const float4*)(xa + o);
    float4 gv = *(const float4*)(xg + o);
    float4 r;
    r.x = cgd * v[0] + ca * av.x + cb * gv.x;
    r.y = cgd * v[1] + ca * av.y + cb * gv.y;
    r.z = cgd * v[2] + ca * av.z + cb * gv.z;
    r.w = cgd * v[3] + ca * av.w + cb * gv.w;
    *(float4*)(out + o) = r;
    if (outh) {
        uint2 hv;
        *(__half2*)&hv.x = __floats2half2_rn(r.x, r.y);
        *(__half2*)&hv.y = __floats2half2_rn(r.z, r.w);
        *(uint2*)(outh + o) = hv;
    }
}

// ---------------- final gather ----------------
__global__ void gather_kernel(const float* __restrict__ x,
                              const int* __restrict__ bn,
                              float* __restrict__ out) {
    int t = blockIdx.x * blockDim.x + threadIdx.x;
    if (t >= BB * RR * 32) return;
    int q = t & 31;
    int r = (t >> 5) % RR;
    int b = t / (32 * RR);
    int node = bn[b];
    ((float4*)out)[(size_t)b * (RR * CC / 4) + r * (CC / 4) + q] =
        ((const float4*)x)[((size_t)r * NN + node) * (CC / 4) + q];
}

// ---------------- driver ----------------
extern "C" void kernel_launch(void* const* d_in, const int* in_sizes, int n_in,
                              void* d_out, int out_size) {
    const float* X  = (const float*)d_in[0];
    const int*   EI = (const int*)d_in[1];
    const int*   BN = (const int*)d_in[2];
    const float* W0 = (const float*)d_in[3];
    const float* B0 = (const float*)d_in[4];
    const float* W1 = (const float*)d_in[5];
    const float* B1 = (const float*)d_in[6];
    float* out = (float*)d_out;

    float *P, *Q;
    __half *Ph, *Qh;
    cudaGetSymbolAddress((void**)&P, g_P);
    cudaGetSymbolAddress((void**)&Q, g_Q);
    cudaGetSymbolAddress((void**)&Ph, g_Ph);
    cudaGetSymbolAddress((void**)&Qh, g_Qh);

    const int EB  = (EE + 255) / 256;
    const int ZB  = (RN + 255) / 256;
    const int SCB = (RN + 1023) / 1024;
    const int SB  = (RN * 32 + 255) / 256;
    const int GB  = (NN + 127) / 128;
    const int PB  = ((RN * CC / 8) + 255) / 256;

    const float dt2  = DTC * DTC;
    const float dt2h = 0.5f * dt2;

    // CSC build interleaved with GEMM (gemm is independent; placed 4th for ncu capture)
    zero_kernel<<<ZB, 256>>>();
    hist_kernel<<<dim3(EB, RR), 256>>>(EI);
    scanA_kernel<<<SCB, 1024>>>();
    gemm_kernel<<<dim3(GB, 2 * RR), 256>>>(X, W0, B0, W1, B1);   // phi0->P, phi1->Q
    scanB_kernel<<<1, 256>>>(SCB);
    scanC_kernel<<<ZB, 256>>>();
    scatter_kernel<<<dim3(EB, RR), 256>>>(EI);
    p2h_kernel<<<PB, 256>>>();                                   // P -> Ph

    // x1 = dt*phi1 + (dt^2/2)*Ahat phi0 + phi0
    spmm_kernel<<<SB, 256>>>(Ph, P, Q, Q, Qh, dt2h, DTC, 1.0f);
    // xn = dt^2*Ahat xc + 2 xc - xp
    spmm_kernel<<<SB, 256>>>(Qh, Q, P, P, Ph, dt2, -1.0f, 2.0f);
    spmm_kernel<<<SB, 256>>>(Ph, P, Q, Q, Qh, dt2, -1.0f, 2.0f);
    spmm_kernel<<<SB, 256>>>(Qh, Q, P, P, nullptr, dt2, -1.0f, 2.0f);

    gather_kernel<<<(BB * RR * 32 + 255) / 256, 256>>>(P, BN, out);
}

// round 10
// speedup vs baseline: 2.0937x; 1.0499x over previous
#include <cuda_runtime.h>
#include <cuda_fp16.h>
#include <cstdint>

#define NN 50000
#define EE 800000
#define RR 3
#define FIN 256
#define CC 128
#define BB 4096
#define DTC 0.25f

#define RN (RR * NN)          // 150000 merged nodes
#define RE (RR * EE)          // 2400000 merged edges

// ---------------- static scratch ----------------
__device__ __align__(16) float  g_P[(size_t)RN * CC];   // ping (fp32)
__device__ __align__(16) float  g_Q[(size_t)RN * CC];   // pong (fp32)
__device__ __align__(16) __half g_Ph[(size_t)RN * CC];  // fp16 shadow of P
__device__ __align__(16) __half g_Qh[(size_t)RN * CC];  // fp16 shadow of Q
__device__ int   g_cnt[RN];
__device__ int   g_ptr[RN + 1];
__device__ int   g_cur[RN];
__device__ float g_dinv[RN];
__device__ __align__(8) int2 g_edge[RE];  // {global src row, bitcast fp32 dinv[src]}
__device__ int   g_bsum[256];
__device__ int   g_boff[256];

// ---------------- CSC build ----------------
__global__ void zero_kernel() {
    int i = blockIdx.x * blockDim.x + threadIdx.x;
    if (i < RN) g_cnt[i] = 0;
}

__global__ void hist_kernel(const int* __restrict__ EI) {
    int e = blockIdx.x * blockDim.x + threadIdx.x;
    int rel = blockIdx.y;
    if (e < EE) {
        int c = EI[(size_t)rel * 2 * EE + EE + e];
        atomicAdd(&g_cnt[rel * NN + c], 1);
    }
}

__global__ void __launch_bounds__(1024) scanA_kernel() {
    __shared__ int sh[1024];
    int t = threadIdx.x;
    int i = blockIdx.x * 1024 + t;
    int v = (i < RN) ? g_cnt[i] : 0;
    sh[t] = v;
    __syncthreads();
    #pragma unroll
    for (int off = 1; off < 1024; off <<= 1) {
        int add = (t >= off) ? sh[t - off] : 0;
        __syncthreads();
        sh[t] += add;
        __syncthreads();
    }
    if (i < RN) g_ptr[i] = sh[t] - v;
    if (t == 1023) g_bsum[blockIdx.x] = sh[t];
}

__global__ void __launch_bounds__(256) scanB_kernel(int nblocks) {
    __shared__ int sh[256];
    int t = threadIdx.x;
    int v = (t < nblocks) ? g_bsum[t] : 0;
    sh[t] = v;
    __syncthreads();
    #pragma unroll
    for (int off = 1; off < 256; off <<= 1) {
        int add = (t >= off) ? sh[t - off] : 0;
        __syncthreads();
        sh[t] += add;
        __syncthreads();
    }
    if (t < nblocks) g_boff[t] = sh[t] - v;
}

__global__ void scanC_kernel() {
    int i = blockIdx.x * blockDim.x + threadIdx.x;
    if (i < RN) {
        int p = g_ptr[i] + g_boff[i >> 10];
        g_ptr[i] = p;
        g_cur[i] = p;
        int c = g_cnt[i];
        g_dinv[i] = (c > 0) ? (1.0f / sqrtf((float)c)) : 0.0f;
    }
    if (i == 0) g_ptr[RN] = RE;
}

__global__ void scatter_kernel(const int* __restrict__ EI) {
    int e = blockIdx.x * blockDim.x + threadIdx.x;
    int rel = blockIdx.y;
    if (e < EE) {
        const int* base = EI + (size_t)rel * 2 * EE;
        int s = rel * NN + base[e];
        int c = base[EE + e];
        int p = atomicAdd(&g_cur[rel * NN + c], 1);
        g_edge[p] = make_int2(s, __float_as_int(g_dinv[s]));
    }
}

// ---------------- fp16 ldmatrix MMA GEMM: phi = X @ W^T + b ----------------
// grid (ceil(NN/128), 6). Block tile 128x128, K slabs of 64 halves.
// 8 warps as 4(m) x 2(n); warp tile 32x64; mma m16n8k16 (fp16 in, fp32 acc).
// smem rows: 64 halves = 128B; swizzle: 16B-chunk c -> c ^ (row & 7).

__device__ __forceinline__ unsigned packh2(float a, float b) {
    __half2 h = __floats2half2_rn(a, b);
    return *(unsigned*)&h;
}

__global__ void __launch_bounds__(256) gemm_kernel(const float* __restrict__ X,
                                                   const float* __restrict__ W0,
                                                   const float* __restrict__ B0,
                                                   const float* __restrict__ W1,
                                                   const float* __restrict__ B1) {
    int rel   = blockIdx.y >> 1;
    int which = blockIdx.y & 1;
    const float* W  = (which ? W1 : W0) + (size_t)rel * CC * FIN;
    const float* Bv = (which ? B1 : B0) + (size_t)rel * CC;
    float* out = (which ? g_Q : g_P) + (size_t)rel * NN * CC;

    __shared__ __align__(16) __half sA[128 * 64];
    __shared__ __align__(16) __half sB[128 * 64];

    int tid  = threadIdx.x;
    int lane = tid & 31;
    int wid  = tid >> 5;
    int m0w  = (wid >> 1) * 32;
    int n0w  = (wid & 1) * 64;
    int rowBase = blockIdx.x * 128;

    // loader: thread t -> row t>>1, 16B-chunks (t&1)*4 .. +3
    int lr   = tid >> 1;
    int lseg = (tid & 1) * 4;
    bool aValid = (rowBase + lr) < NN;
    const float* Xrow = X + (size_t)(aValid ? (rowBase + lr) : 0) * FIN;
    const float* Wrow = W + (size_t)lr * FIN;

    unsigned sAu = (unsigned)__cvta_generic_to_shared(sA);
    unsigned sBu = (unsigned)__cvta_generic_to_shared(sB);

    float d[2][8][4];
    #pragma unroll
    for (int mt = 0; mt < 2; mt++)
        #pragma unroll
        for (int nt = 0; nt < 8; nt++)
            #pragma unroll
            for (int i = 0; i < 4; i++) d[mt][nt][i] = 0.0f;

    for (int ks = 0; ks < FIN; ks += 64) {
        // ---- load slab (fp32 -> fp16, swizzled) ----
        #pragma unroll
        for (int j = 0; j < 4; j++) {
            int chunk = lseg + j;             // 0..7 (16B chunks of the 128B row)
            int hoff  = ks + chunk * 8;       // first k index of this chunk
            float4 f0 = make_float4(0.f, 0.f, 0.f, 0.f), f1 = f0;
            if (aValid) {
                f0 = *(const float4*)(Xrow + hoff);
                f1 = *(const float4*)(Xrow + hoff + 4);
            }
            float4 g0 = *(const float4*)(Wrow + hoff);
            float4 g1 = *(const float4*)(Wrow + hoff + 4);
            uint4 ha, hb;
            ha.x = packh2(f0.x, f0.y); ha.y = packh2(f0.z, f0.w);
            ha.z = packh2(f1.x, f1.y); ha.w = packh2(f1.z, f1.w);
            hb.x = packh2(g0.x, g0.y); hb.y = packh2(g0.z, g0.w);
            hb.z = packh2(g1.x, g1.y); hb.w = packh2(g1.z, g1.w);
            int cs = chunk ^ (lr & 7);
            *(uint4*)(sA + lr * 64 + cs * 8) = ha;
            *(uint4*)(sB + lr * 64 + cs * 8) = hb;
        }
        __syncthreads();

        // ---- compute 4 k-chunks of 16 ----
        #pragma unroll
        for (int kc = 0; kc < 4; kc++) {
            unsigned a0[4], a1[4];
            {
                int row = m0w + (lane & 15);
                int c   = kc * 2 + (lane >> 4);
                int cs  = c ^ (row & 7);
                unsigned addr = sAu + (unsigned)(row * 128 + cs * 16);
                asm volatile("ldmatrix.sync.aligned.m8n8.x4.shared.b16 {%0,%1,%2,%3}, [%4];"
                    : "=r"(a0[0]), "=r"(a0[1]), "=r"(a0[2]), "=r"(a0[3])
                    : "r"(addr));
            }
            {
                int row = m0w + 16 + (lane & 15);
                int c   = kc * 2 + (lane >> 4);
                int cs  = c ^ (row & 7);
                unsigned addr = sAu + (unsigned)(row * 128 + cs * 16);
                asm volatile("ldmatrix.sync.aligned.m8n8.x4.shared.b16 {%0,%1,%2,%3}, [%4];"
                    : "=r"(a1[0]), "=r"(a1[1]), "=r"(a1[2]), "=r"(a1[3])
                    : "r"(addr));
            }
            #pragma unroll
            for (int np = 0; np < 4; np++) {
                int quad = lane >> 3;
                int row  = n0w + np * 16 + (quad >> 1) * 8 + (lane & 7);
                int c    = kc * 2 + (quad & 1);
                int cs   = c ^ (row & 7);
                unsigned addr = sBu + (unsigned)(row * 128 + cs * 16);
                unsigned b0, b1, b2, b3;
                asm volatile("ldmatrix.sync.aligned.m8n8.x4.shared.b16 {%0,%1,%2,%3}, [%4];"
                    : "=r"(b0), "=r"(b1), "=r"(b2), "=r"(b3) : "r"(addr));
                asm volatile(
                    "mma.sync.aligned.m16n8k16.row.col.f32.f16.f16.f32 "
                    "{%0,%1,%2,%3}, {%4,%5,%6,%7}, {%8,%9}, {%0,%1,%2,%3};"
                    : "+f"(d[0][2*np][0]), "+f"(d[0][2*np][1]),
                      "+f"(d[0][2*np][2]), "+f"(d[0][2*np][3])
                    : "r"(a0[0]), "r"(a0[1]), "r"(a0[2]), "r"(a0[3]),
                      "r"(b0), "r"(b1));
                asm volatile(
                    "mma.sync.aligned.m16n8k16.row.col.f32.f16.f16.f32 "
                    "{%0,%1,%2,%3}, {%4,%5,%6,%7}, {%8,%9}, {%0,%1,%2,%3};"
                    : "+f"(d[0][2*np+1][0]), "+f"(d[0][2*np+1][1]),
                      "+f"(d[0][2*np+1][2]), "+f"(d[0][2*np+1][3])
                    : "r"(a0[0]), "r"(a0[1]), "r"(a0[2]), "r"(a0[3]),
                      "r"(b2), "r"(b3));
                asm volatile(
                    "mma.sync.aligned.m16n8k16.row.col.f32.f16.f16.f32 "
                    "{%0,%1,%2,%3}, {%4,%5,%6,%7}, {%8,%9}, {%0,%1,%2,%3};"
                    : "+f"(d[1][2*np][0]), "+f"(d[1][2*np][1]),
                      "+f"(d[1][2*np][2]), "+f"(d[1][2*np][3])
                    : "r"(a1[0]), "r"(a1[1]), "r"(a1[2]), "r"(a1[3]),
                      "r"(b0), "r"(b1));
                asm volatile(
                    "mma.sync.aligned.m16n8k16.row.col.f32.f16.f16.f32 "
                    "{%0,%1,%2,%3}, {%4,%5,%6,%7}, {%8,%9}, {%0,%1,%2,%3};"
                    : "+f"(d[1][2*np+1][0]), "+f"(d[1][2*np+1][1]),
                      "+f"(d[1][2*np+1][2]), "+f"(d[1][2*np+1][3])
                    : "r"(a1[0]), "r"(a1[1]), "r"(a1[2]), "r"(a1[3]),
                      "r"(b2), "r"(b3));
            }
        }
        __syncthreads();
    }

    // epilogue: lane l -> gid=l>>2 (row), tig=l&3 (col pair); d0,d1 row m, d2,d3 row m+8
    int gid = lane >> 2, tig = lane & 3;
    #pragma unroll
    for (int mt = 0; mt < 2; mt++) {
        int r0 = rowBase + m0w + mt * 16 + gid;
        int r1 = r0 + 8;
        #pragma unroll
        for (int nt = 0; nt < 8; nt++) {
            int cidx = n0w + nt * 8 + tig * 2;
            float bx = Bv[cidx], by = Bv[cidx + 1];
            if (r0 < NN)
                *(float2*)(out + (size_t)r0 * CC + cidx) =
                    make_float2(d[mt][nt][0] + bx, d[mt][nt][1] + by);
            if (r1 < NN)
                *(float2*)(out + (size_t)r1 * CC + cidx) =
                    make_float2(d[mt][nt][2] + bx, d[mt][nt][3] + by);
        }
    }
}

// ---------------- coalesced fp32 -> fp16 shadow convert (P -> Ph) ----------------
__global__ void p2h_kernel() {
    size_t i = (size_t)blockIdx.x * blockDim.x + threadIdx.x;
    if (i >= (size_t)RN * CC / 8) return;
    const float4* src = (const float4*)g_P;
    float4 a = src[i * 2];
    float4 b = src[i * 2 + 1];
    uint4 h;
    h.x = packh2(a.x, a.y); h.y = packh2(a.z, a.w);
    h.z = packh2(b.x, b.y); h.w = packh2(b.z, b.w);
    ((uint4*)g_Ph)[i] = h;
}

// ---------------- fused SpMM + wave update (4 edges/warp-iter, fp16 gather) ----------------
// out[i,c] = cg*dinv[i]*sum_s dinv[s]*xgh[s,c] + ca*xa[i,c] + cb*xg[i,c]
__global__ void __launch_bounds__(256) spmm_kernel(const __half* __restrict__ xgh,
                                                   const float*  __restrict__ xg,
                                                   const float*  __restrict__ xa,
                                                   float*  __restrict__ out,
                                                   __half* __restrict__ outh,
                                                   float cg, float ca, float cb) {
    int w    = (blockIdx.x * blockDim.x + threadIdx.x) >> 5;  // global dst row
    int lane = threadIdx.x & 31;
    if (w >= RN) return;
    int p0 = g_ptr[w], p1 = g_ptr[w + 1];
    int hw = lane >> 4;                   // half-warp id
    int hl = lane & 15;                   // 16 lanes x 8 fp16 channels

    float acc[8];
    #pragma unroll
    for (int i = 0; i < 8; i++) acc[i] = 0.0f;

    // half-warp hw handles edge pairs (k, k+1) at k = p0 + 2*hw, step 4 -> MLP 4 loads/iter
    int k = p0 + 2 * hw;
    for (; k + 1 < p1; k += 4) {
        int2 e0 = __ldg(&g_edge[k]);
        int2 e1 = __ldg(&g_edge[k + 1]);
        uint4 h0 = *(const uint4*)(xgh + (size_t)e0.x * CC + hl * 8);
        uint4 h1 = *(const uint4*)(xgh + (size_t)e1.x * CC + hl * 8);
        float w0 = __int_as_float(e0.y);
        float w1 = __int_as_float(e1.y);
        float2 f;
        f = __half22float2(*(__half2*)&h0.x); acc[0] += w0 * f.x; acc[1] += w0 * f.y;
        f = __half22float2(*(__half2*)&h0.y); acc[2] += w0 * f.x; acc[3] += w0 * f.y;
        f = __half22float2(*(__half2*)&h0.z); acc[4] += w0 * f.x; acc[5] += w0 * f.y;
        f = __half22float2(*(__half2*)&h0.w); acc[6] += w0 * f.x; acc[7] += w0 * f.y;
        f = __half22float2(*(__half2*)&h1.x); acc[0] += w1 * f.x; acc[1] += w1 * f.y;
        f = __half22float2(*(__half2*)&h1.y); acc[2] += w1 * f.x; acc[3] += w1 * f.y;
        f = __half22float2(*(__half2*)&h1.z); acc[4] += w1 * f.x; acc[5] += w1 * f.y;
        f = __half22float2(*(__half2*)&h1.w); acc[6] += w1 * f.x; acc[7] += w1 * f.y;
    }
    if (k < p1) {                         // odd leftover for this half-warp
        int2 e0 = __ldg(&g_edge[k]);
        uint4 h0 = *(const uint4*)(xgh + (size_t)e0.x * CC + hl * 8);
        float w0 = __int_as_float(e0.y);
        float2 f;
        f = __half22float2(*(__half2*)&h0.x); acc[0] += w0 * f.x; acc[1] += w0 * f.y;
        f = __half22float2(*(__half2*)&h0.y); acc[2] += w0 * f.x; acc[3] += w0 * f.y;
        f = __half22float2(*(__half2*)&h0.z); acc[4] += w0 * f.x; acc[5] += w0 * f.y;
        f = __half22float2(*(__half2*)&h0.w); acc[6] += w0 * f.x; acc[7] += w0 * f.y;
    }

    // combine the two half-warps: lanes 0-15 get full sums for chans hl*8..hl*8+7
    #pragma unroll
    for (int i = 0; i < 8; i++) acc[i] += __shfl_down_sync(0xffffffffu, acc[i], 16);
    // redistribute so lane m holds channels m*4..m*4+3 (coalesced fp32 epilogue)
    float v[4];
    #pragma unroll
    for (int j = 0; j < 4; j++) {
        float t0 = __shfl_sync(0xffffffffu, acc[j],     lane >> 1);
        float t1 = __shfl_sync(0xffffffffu, acc[4 + j], lane >> 1);
        v[j] = (lane & 1) ? t1 : t0;
    }

    float cgd = cg * g_dinv[w];
    size_t o = (size_t)w * CC + lane * 4;
    float4 av = *(const float4*)(xa + o);
    float4 gv = *(const float4*)(xg + o);
    float4 r;
    r.x = cgd * v[0] + ca * av.x + cb * gv.x;
    r.y = cgd * v[1] + ca * av.y + cb * gv.y;
    r.z = cgd * v[2] + ca * av.z + cb * gv.z;
    r.w = cgd * v[3] + ca * av.w + cb * gv.w;
    *(float4*)(out + o) = r;
    if (outh) {
        uint2 hv;
        hv.x = packh2(r.x, r.y);
        hv.y = packh2(r.z, r.w);
        *(uint2*)(outh + o) = hv;
    }
}

// ---------------- final gather ----------------
__global__ void gather_kernel(const float* __restrict__ x,
                              const int* __restrict__ bn,
                              float* __restrict__ out) {
    int t = blockIdx.x * blockDim.x + threadIdx.x;
    if (t >= BB * RR * 32) return;
    int q = t & 31;
    int r = (t >> 5) % RR;
    int b = t / (32 * RR);
    int node = bn[b];
    ((float4*)out)[(size_t)b * (RR * CC / 4) + r * (CC / 4) + q] =
        ((const float4*)x)[((size_t)r * NN + node) * (CC / 4) + q];
}

// ---------------- driver ----------------
extern "C" void kernel_launch(void* const* d_in, const int* in_sizes, int n_in,
                              void* d_out, int out_size) {
    const float* X  = (const float*)d_in[0];
    const int*   EI = (const int*)d_in[1];
    const int*   BN = (const int*)d_in[2];
    const float* W0 = (const float*)d_in[3];
    const float* B0 = (const float*)d_in[4];
    const float* W1 = (const float*)d_in[5];
    const float* B1 = (const float*)d_in[6];
    float* out = (float*)d_out;

    float *P, *Q;
    __half *Ph, *Qh;
    cudaGetSymbolAddress((void**)&P, g_P);
    cudaGetSymbolAddress((void**)&Q, g_Q);
    cudaGetSymbolAddress((void**)&Ph, g_Ph);
    cudaGetSymbolAddress((void**)&Qh, g_Qh);

    const int EB  = (EE + 255) / 256;
    const int ZB  = (RN + 255) / 256;
    const int SCB = (RN + 1023) / 1024;
    const int SB  = (RN * 32 + 255) / 256;
    const int GB  = (NN + 127) / 128;
    const int PB  = ((RN * CC / 8) + 255) / 256;

    const float dt2  = DTC * DTC;
    const float dt2h = 0.5f * dt2;

    zero_kernel<<<ZB, 256>>>();
    hist_kernel<<<dim3(EB, RR), 256>>>(EI);
    scanA_kernel<<<SCB, 1024>>>();
    gemm_kernel<<<dim3(GB, 2 * RR), 256>>>(X, W0, B0, W1, B1);   // phi0->P, phi1->Q
    scanB_kernel<<<1, 256>>>(SCB);
    scanC_kernel<<<ZB, 256>>>();
    scatter_kernel<<<dim3(EB, RR), 256>>>(EI);
    p2h_kernel<<<PB, 256>>>();                                   // P -> Ph

    // x1 = dt*phi1 + (dt^2/2)*Ahat phi0 + phi0
    spmm_kernel<<<SB, 256>>>(Ph, P, Q, Q, Qh, dt2h, DTC, 1.0f);
    // xn = dt^2*Ahat xc + 2 xc - xp
    spmm_kernel<<<SB, 256>>>(Qh, Q, P, P, Ph, dt2, -1.0f, 2.0f);
    spmm_kernel<<<SB, 256>>>(Ph, P, Q, Q, Qh, dt2, -1.0f, 2.0f);
    spmm_kernel<<<SB, 256>>>(Qh, Q, P, P, nullptr, dt2, -1.0f, 2.0f);

    gather_kernel<<<(BB * RR * 32 + 255) / 256, 256>>>(P, BN, out);
}

// round 11
// speedup vs baseline: 2.6031x; 1.2433x over previous
#include <cuda_runtime.h>
#include <cuda_fp16.h>
#include <cstdint>

#define NN 50000
#define EE 800000
#define RR 3
#define FIN 256
#define CC 128
#define BB 4096
#define DTC 0.25f

#define RN (RR * NN)          // 150000 merged nodes
#define RE (RR * EE)          // 2400000 merged edges
#define GBK 391               // gemm row blocks (ceil(NN/128))

// ---------------- static scratch ----------------
__device__ __align__(16) float  g_P[(size_t)RN * CC];   // ping (fp32)
__device__ __align__(16) float  g_Q[(size_t)RN * CC];   // pong (fp32)
__device__ __align__(16) __half g_Ph[(size_t)RN * CC];  // fp16 shadow of P
__device__ __align__(16) __half g_Qh[(size_t)RN * CC];  // fp16 shadow of Q
__device__ int   g_cnt[RN];
__device__ int   g_ptr[RN + 1];
__device__ int   g_cur[RN];
__device__ float g_dinv[RN];
__device__ __align__(8) int2 g_edge[RE];  // {global src row, bitcast fp32 dinv[src]}
__device__ int   g_bsum[256];
__device__ int   g_boff[256];
// pre-swizzled fp16 operand images: [blk][slab][row][8 x 16B chunks]
__device__ __align__(16) uint4 g_Xh[(size_t)GBK * 4096];  // 391*4 slabs*1024 chunks
__device__ __align__(16) uint4 g_Wh[6 * 4096];            // 6 mats * 4 slabs * 1024

// ---------------- CSC build ----------------
__global__ void zero_kernel() {
    int i = blockIdx.x * blockDim.x + threadIdx.x;
    if (i < RN) g_cnt[i] = 0;
}

__global__ void hist_kernel(const int* __restrict__ EI) {
    int e = blockIdx.x * blockDim.x + threadIdx.x;
    int rel = blockIdx.y;
    if (e < EE) {
        int c = EI[(size_t)rel * 2 * EE + EE + e];
        atomicAdd(&g_cnt[rel * NN + c], 1);
    }
}

__global__ void __launch_bounds__(1024) scanA_kernel() {
    __shared__ int sh[1024];
    int t = threadIdx.x;
    int i = blockIdx.x * 1024 + t;
    int v = (i < RN) ? g_cnt[i] : 0;
    sh[t] = v;
    __syncthreads();
    #pragma unroll
    for (int off = 1; off < 1024; off <<= 1) {
        int add = (t >= off) ? sh[t - off] : 0;
        __syncthreads();
        sh[t] += add;
        __syncthreads();
    }
    if (i < RN) g_ptr[i] = sh[t] - v;
    if (t == 1023) g_bsum[blockIdx.x] = sh[t];
}

__global__ void __launch_bounds__(256) scanB_kernel(int nblocks) {
    __shared__ int sh[256];
    int t = threadIdx.x;
    int v = (t < nblocks) ? g_bsum[t] : 0;
    sh[t] = v;
    __syncthreads();
    #pragma unroll
    for (int off = 1; off < 256; off <<= 1) {
        int add = (t >= off) ? sh[t - off] : 0;
        __syncthreads();
        sh[t] += add;
        __syncthreads();
    }
    if (t < nblocks) g_boff[t] = sh[t] - v;
}

__global__ void scanC_kernel() {
    int i = blockIdx.x * blockDim.x + threadIdx.x;
    if (i < RN) {
        int p = g_ptr[i] + g_boff[i >> 10];
        g_ptr[i] = p;
        g_cur[i] = p;
        int c = g_cnt[i];
        g_dinv[i] = (c > 0) ? (1.0f / sqrtf((float)c)) : 0.0f;
    }
    if (i == 0) g_ptr[RN] = RE;
}

__global__ void scatter_kernel(const int* __restrict__ EI) {
    int e = blockIdx.x * blockDim.x + threadIdx.x;
    int rel = blockIdx.y;
    if (e < EE) {
        const int* base = EI + (size_t)rel * 2 * EE;
        int s = rel * NN + base[e];
        int c = base[EE + e];
        int p = atomicAdd(&g_cur[rel * NN + c], 1);
        g_edge[p] = make_int2(s, __float_as_int(g_dinv[s]));
    }
}

// ---------------- fp16 operand prep (convert + swizzle once) ----------------
__device__ __forceinline__ unsigned packh2(float a, float b) {
    __half2 h = __floats2half2_rn(a, b);
    return *(unsigned*)&h;
}

// one thread per 16B output chunk. chunk image: row*8 + (chunk ^ (row&7))
__global__ void prepx_kernel(const float* __restrict__ X) {
    int t = blockIdx.x * blockDim.x + threadIdx.x;
    if (t >= GBK * 4096) return;
    int chunk = t & 7;
    int row   = (t >> 3) & 127;
    int slab  = (t >> 10) & 3;
    int blk   = t >> 12;
    int grow  = blk * 128 + row;
    uint4 o = make_uint4(0u, 0u, 0u, 0u);
    if (grow < NN) {
        const float* src = X + (size_t)grow * FIN + slab * 64 + chunk * 8;
        float4 f0 = *(const float4*)src;
        float4 f1 = *(const float4*)(src + 4);
        o.x = packh2(f0.x, f0.y); o.y = packh2(f0.z, f0.w);
        o.z = packh2(f1.x, f1.y); o.w = packh2(f1.z, f1.w);
    }
    int cs = chunk ^ (row & 7);
    g_Xh[(size_t)((blk * 4 + slab) * 128 + row) * 8 + cs] = o;
}

__global__ void prepw_kernel(const float* __restrict__ W0,
                             const float* __restrict__ W1) {
    int t = blockIdx.x * blockDim.x + threadIdx.x;
    if (t >= 6 * 4096) return;
    int chunk = t & 7;
    int row   = (t >> 3) & 127;
    int slab  = (t >> 10) & 3;
    int mat   = t >> 12;             // = blockIdx.y of gemm
    int rel = mat >> 1, which = mat & 1;
    const float* W = (which ? W1 : W0) + (size_t)rel * CC * FIN;
    const float* src = W + (size_t)row * FIN + slab * 64 + chunk * 8;
    float4 f0 = *(const float4*)src;
    float4 f1 = *(const float4*)(src + 4);
    uint4 o;
    o.x = packh2(f0.x, f0.y); o.y = packh2(f0.z, f0.w);
    o.z = packh2(f1.x, f1.y); o.w = packh2(f1.z, f1.w);
    int cs = chunk ^ (row & 7);
    g_Wh[((mat * 4 + slab) * 128 + row) * 8 + cs] = o;
}

// ---------------- fp16 MMA GEMM with cp.async double buffering ----------------
// dynamic smem: [bufA0 16KB][bufA1 16KB][bufB0 16KB][bufB1 16KB] = 64KB
__global__ void __launch_bounds__(256) gemm_kernel(const float* __restrict__ B0,
                                                   const float* __restrict__ B1) {
    extern __shared__ __align__(16) char dsmem[];
    int rel   = blockIdx.y >> 1;
    int which = blockIdx.y & 1;
    const float* Bv = (which ? B1 : B0) + (size_t)rel * CC;
    float* out = (which ? g_Q : g_P) + (size_t)rel * NN * CC;

    const uint4* Xs = g_Xh + (size_t)blockIdx.x * 4096;
    const uint4* Ws = g_Wh + (size_t)blockIdx.y * 4096;

    int tid  = threadIdx.x;
    int lane = tid & 31;
    int wid  = tid >> 5;
    int m0w  = (wid >> 1) * 32;
    int n0w  = (wid & 1) * 64;
    int rowBase = blockIdx.x * 128;

    unsigned dynu = (unsigned)__cvta_generic_to_shared(dsmem);

    float d[2][8][4];
    #pragma unroll
    for (int mt = 0; mt < 2; mt++)
        #pragma unroll
        for (int nt = 0; nt < 8; nt++)
            #pragma unroll
            for (int i = 0; i < 4; i++) d[mt][nt][i] = 0.0f;

    // prefetch: copy slab s into buffer buf (pure linear 16B copies)
    auto prefetch = [&](int s, int buf) {
        const uint4* srcA = Xs + s * 1024 + tid;
        const uint4* srcB = Ws + s * 1024 + tid;
        unsigned dA = dynu + buf * 16384 + tid * 16;
        unsigned dB = dynu + 32768 + buf * 16384 + tid * 16;
        #pragma unroll
        for (int j = 0; j < 4; j++) {
            asm volatile("cp.async.cg.shared.global [%0], [%1], 16;"
                         :: "r"(dA + j * 4096), "l"(srcA + j * 256));
            asm volatile("cp.async.cg.shared.global [%0], [%1], 16;"
                         :: "r"(dB + j * 4096), "l"(srcB + j * 256));
        }
    };

    prefetch(0, 0);
    asm volatile("cp.async.commit_group;");

    #pragma unroll
    for (int s = 0; s < 4; s++) {
        if (s < 3) {
            prefetch(s + 1, (s + 1) & 1);
            asm volatile("cp.async.commit_group;");
            asm volatile("cp.async.wait_group 1;");
        } else {
            asm volatile("cp.async.wait_group 0;");
        }
        __syncthreads();

        unsigned sAu = dynu + (s & 1) * 16384;
        unsigned sBu = dynu + 32768 + (s & 1) * 16384;

        #pragma unroll
        for (int kc = 0; kc < 4; kc++) {
            unsigned a0[4], a1[4];
            {
                int row = m0w + (lane & 15);
                int c   = kc * 2 + (lane >> 4);
                int cs  = c ^ (row & 7);
                unsigned addr = sAu + (unsigned)(row * 128 + cs * 16);
                asm volatile("ldmatrix.sync.aligned.m8n8.x4.shared.b16 {%0,%1,%2,%3}, [%4];"
                    : "=r"(a0[0]), "=r"(a0[1]), "=r"(a0[2]), "=r"(a0[3])
                    : "r"(addr));
            }
            {
                int row = m0w + 16 + (lane & 15);
                int c   = kc * 2 + (lane >> 4);
                int cs  = c ^ (row & 7);
                unsigned addr = sAu + (unsigned)(row * 128 + cs * 16);
                asm volatile("ldmatrix.sync.aligned.m8n8.x4.shared.b16 {%0,%1,%2,%3}, [%4];"
                    : "=r"(a1[0]), "=r"(a1[1]), "=r"(a1[2]), "=r"(a1[3])
                    : "r"(addr));
            }
            #pragma unroll
            for (int np = 0; np < 4; np++) {
                int quad = lane >> 3;
                int row  = n0w + np * 16 + (quad >> 1) * 8 + (lane & 7);
                int c    = kc * 2 + (quad & 1);
                int cs   = c ^ (row & 7);
                unsigned addr = sBu + (unsigned)(row * 128 + cs * 16);
                unsigned b0, b1, b2, b3;
                asm volatile("ldmatrix.sync.aligned.m8n8.x4.shared.b16 {%0,%1,%2,%3}, [%4];"
                    : "=r"(b0), "=r"(b1), "=r"(b2), "=r"(b3) : "r"(addr));
                asm volatile(
                    "mma.sync.aligned.m16n8k16.row.col.f32.f16.f16.f32 "
                    "{%0,%1,%2,%3}, {%4,%5,%6,%7}, {%8,%9}, {%0,%1,%2,%3};"
                    : "+f"(d[0][2*np][0]), "+f"(d[0][2*np][1]),
                      "+f"(d[0][2*np][2]), "+f"(d[0][2*np][3])
                    : "r"(a0[0]), "r"(a0[1]), "r"(a0[2]), "r"(a0[3]),
                      "r"(b0), "r"(b1));
                asm volatile(
                    "mma.sync.aligned.m16n8k16.row.col.f32.f16.f16.f32 "
                    "{%0,%1,%2,%3}, {%4,%5,%6,%7}, {%8,%9}, {%0,%1,%2,%3};"
                    : "+f"(d[0][2*np+1][0]), "+f"(d[0][2*np+1][1]),
                      "+f"(d[0][2*np+1][2]), "+f"(d[0][2*np+1][3])
                    : "r"(a0[0]), "r"(a0[1]), "r"(a0[2]), "r"(a0[3]),
                      "r"(b2), "r"(b3));
                asm volatile(
                    "mma.sync.aligned.m16n8k16.row.col.f32.f16.f16.f32 "
                    "{%0,%1,%2,%3}, {%4,%5,%6,%7}, {%8,%9}, {%0,%1,%2,%3};"
                    : "+f"(d[1][2*np][0]), "+f"(d[1][2*np][1]),
                      "+f"(d[1][2*np][2]), "+f"(d[1][2*np][3])
                    : "r"(a1[0]), "r"(a1[1]), "r"(a1[2]), "r"(a1[3]),
                      "r"(b0), "r"(b1));
                asm volatile(
                    "mma.sync.aligned.m16n8k16.row.col.f32.f16.f16.f32 "
                    "{%0,%1,%2,%3}, {%4,%5,%6,%7}, {%8,%9}, {%0,%1,%2,%3};"
                    : "+f"(d[1][2*np+1][0]), "+f"(d[1][2*np+1][1]),
                      "+f"(d[1][2*np+1][2]), "+f"(d[1][2*np+1][3])
                    : "r"(a1[0]), "r"(a1[1]), "r"(a1[2]), "r"(a1[3]),
                      "r"(b2), "r"(b3));
            }
        }
        __syncthreads();
    }

    // epilogue
    int gid = lane >> 2, tig = lane & 3;
    #pragma unroll
    for (int mt = 0; mt < 2; mt++) {
        int r0 = rowBase + m0w + mt * 16 + gid;
        int r1 = r0 + 8;
        #pragma unroll
        for (int nt = 0; nt < 8; nt++) {
            int cidx = n0w + nt * 8 + tig * 2;
            float bx = Bv[cidx], by = Bv[cidx + 1];
            if (r0 < NN)
                *(float2*)(out + (size_t)r0 * CC + cidx) =
                    make_float2(d[mt][nt][0] + bx, d[mt][nt][1] + by);
            if (r1 < NN)
                *(float2*)(out + (size_t)r1 * CC + cidx) =
                    make_float2(d[mt][nt][2] + bx, d[mt][nt][3] + by);
        }
    }
}

// ---------------- coalesced fp32 -> fp16 shadow convert (P -> Ph) ----------------
__global__ void p2h_kernel() {
    size_t i = (size_t)blockIdx.x * blockDim.x + threadIdx.x;
    if (i >= (size_t)RN * CC / 8) return;
    const float4* src = (const float4*)g_P;
    float4 a = src[i * 2];
    float4 b = src[i * 2 + 1];
    uint4 h;
    h.x = packh2(a.x, a.y); h.y = packh2(a.z, a.w);
    h.z = packh2(b.x, b.y); h.w = packh2(b.z, b.w);
    ((uint4*)g_Ph)[i] = h;
}

// ---------------- fused SpMM + wave update (4 loads in flight, fp16 gather) ----------------
__global__ void __launch_bounds__(256) spmm_kernel(const __half* __restrict__ xgh,
                                                   const float*  __restrict__ xg,
                                                   const float*  __restrict__ xa,
                                                   float*  __restrict__ out,
                                                   __half* __restrict__ outh,
                                                   float cg, float ca, float cb) {
    int w    = (blockIdx.x * blockDim.x + threadIdx.x) >> 5;  // global dst row
    int lane = threadIdx.x & 31;
    if (w >= RN) return;
    int p0 = g_ptr[w], p1 = g_ptr[w + 1];
    int hw = lane >> 4;                   // half-warp id
    int hl = lane & 15;                   // 16 lanes x 8 fp16 channels

    float acc[8];
    #pragma unroll
    for (int i = 0; i < 8; i++) acc[i] = 0.0f;

    int k = p0 + 2 * hw;
    for (; k + 1 < p1; k += 4) {
        int2 e0 = __ldg(&g_edge[k]);
        int2 e1 = __ldg(&g_edge[k + 1]);
        uint4 h0 = *(const uint4*)(xgh + (size_t)e0.x * CC + hl * 8);
        uint4 h1 = *(const uint4*)(xgh + (size_t)e1.x * CC + hl * 8);
        float w0 = __int_as_float(e0.y);
        float w1 = __int_as_float(e1.y);
        float2 f;
        f = __half22float2(*(__half2*)&h0.x); acc[0] += w0 * f.x; acc[1] += w0 * f.y;
        f = __half22float2(*(__half2*)&h0.y); acc[2] += w0 * f.x; acc[3] += w0 * f.y;
        f = __half22float2(*(__half2*)&h0.z); acc[4] += w0 * f.x; acc[5] += w0 * f.y;
        f = __half22float2(*(__half2*)&h0.w); acc[6] += w0 * f.x; acc[7] += w0 * f.y;
        f = __half22float2(*(__half2*)&h1.x); acc[0] += w1 * f.x; acc[1] += w1 * f.y;
        f = __half22float2(*(__half2*)&h1.y); acc[2] += w1 * f.x; acc[3] += w1 * f.y;
        f = __half22float2(*(__half2*)&h1.z); acc[4] += w1 * f.x; acc[5] += w1 * f.y;
        f = __half22float2(*(__half2*)&h1.w); acc[6] += w1 * f.x; acc[7] += w1 * f.y;
    }
    if (k < p1) {
        int2 e0 = __ldg(&g_edge[k]);
        uint4 h0 = *(const uint4*)(xgh + (size_t)e0.x * CC + hl * 8);
        float w0 = __int_as_float(e0.y);
        float2 f;
        f = __half22float2(*(__half2*)&h0.x); acc[0] += w0 * f.x; acc[1] += w0 * f.y;
        f = __half22float2(*(__half2*)&h0.y); acc[2] += w0 * f.x; acc[3] += w0 * f.y;
        f = __half22float2(*(__half2*)&h0.z); acc[4] += w0 * f.x; acc[5] += w0 * f.y;
        f = __half22float2(*(__half2*)&h0.w); acc[6] += w0 * f.x; acc[7] += w0 * f.y;
    }

    #pragma unroll
    for (int i = 0; i < 8; i++) acc[i] += __shfl_down_sync(0xffffffffu, acc[i], 16);
    float v[4];
    #pragma unroll
    for (int j = 0; j < 4; j++) {
        float t0 = __shfl_sync(0xffffffffu, acc[j],     lane >> 1);
        float t1 = __shfl_sync(0xffffffffu, acc[4 + j], lane >> 1);
        v[j] = (lane & 1) ? t1 : t0;
    }

    float cgd = cg * g_dinv[w];
    size_t o = (size_t)w * CC + lane * 4;
    float4 av = *(const float4*)(xa + o);
    float4 gv = *(const float4*)(xg + o);
    float4 r;
    r.x = cgd * v[0] + ca * av.x + cb * gv.x;
    r.y = cgd * v[1] + ca * av.y + cb * gv.y;
    r.z = cgd * v[2] + ca * av.z + cb * gv.z;
    r.w = cgd * v[3] + ca * av.w + cb * gv.w;
    *(float4*)(out + o) = r;
    if (outh) {
        uint2 hv;
        hv.x = packh2(r.x, r.y);
        hv.y = packh2(r.z, r.w);
        *(uint2*)(outh + o) = hv;
    }
}

// ---------------- final gather ----------------
__global__ void gather_kernel(const float* __restrict__ x,
                              const int* __restrict__ bn,
                              float* __restrict__ out) {
    int t = blockIdx.x * blockDim.x + threadIdx.x;
    if (t >= BB * RR * 32) return;
    int q = t & 31;
    int r = (t >> 5) % RR;
    int b = t / (32 * RR);
    int node = bn[b];
    ((float4*)out)[(size_t)b * (RR * CC / 4) + r * (CC / 4) + q] =
        ((const float4*)x)[((size_t)r * NN + node) * (CC / 4) + q];
}

// ---------------- driver ----------------
extern "C" void kernel_launch(void* const* d_in, const int* in_sizes, int n_in,
                              void* d_out, int out_size) {
    const float* X  = (const float*)d_in[0];
    const int*   EI = (const int*)d_in[1];
    const int*   BN = (const int*)d_in[2];
    const float* W0 = (const float*)d_in[3];
    const float* B0 = (const float*)d_in[4];
    const float* W1 = (const float*)d_in[5];
    const float* B1 = (const float*)d_in[6];
    float* out = (float*)d_out;

    float *P, *Q;
    __half *Ph, *Qh;
    cudaGetSymbolAddress((void**)&P, g_P);
    cudaGetSymbolAddress((void**)&Q, g_Q);
    cudaGetSymbolAddress((void**)&Ph, g_Ph);
    cudaGetSymbolAddress((void**)&Qh, g_Qh);

    static bool attrSet = false;
    if (!attrSet) {
        cudaFuncSetAttribute(gemm_kernel,
                             cudaFuncAttributeMaxDynamicSharedMemorySize, 65536);
        attrSet = true;
    }

    const int EB  = (EE + 255) / 256;
    const int ZB  = (RN + 255) / 256;
    const int SCB = (RN + 1023) / 1024;
    const int SB  = (RN * 32 + 255) / 256;
    const int PB  = ((RN * CC / 8) + 255) / 256;
    const int PXB = (GBK * 4096 + 255) / 256;

    const float dt2  = DTC * DTC;
    const float dt2h = 0.5f * dt2;

    zero_kernel<<<ZB, 256>>>();
    hist_kernel<<<dim3(EB, RR), 256>>>(EI);
    prepx_kernel<<<PXB, 256>>>(X);
    prepw_kernel<<<(6 * 4096 + 255) / 256, 256>>>(W0, W1);
    scanA_kernel<<<SCB, 1024>>>();
    gemm_kernel<<<dim3(GBK, 2 * RR), 256, 65536>>>(B0, B1);   // phi0->P, phi1->Q
    scanB_kernel<<<1, 256>>>(SCB);
    scanC_kernel<<<ZB, 256>>>();
    scatter_kernel<<<dim3(EB, RR), 256>>>(EI);
    p2h_kernel<<<PB, 256>>>();                                // P -> Ph

    // x1 = dt*phi1 + (dt^2/2)*Ahat phi0 + phi0
    spmm_kernel<<<SB, 256>>>(Ph, P, Q, Q, Qh, dt2h, DTC, 1.0f);
    // xn = dt^2*Ahat xc + 2 xc - xp
    spmm_kernel<<<SB, 256>>>(Qh, Q, P, P, Ph, dt2, -1.0f, 2.0f);
    spmm_kernel<<<SB, 256>>>(Ph, P, Q, Q, Qh, dt2, -1.0f, 2.0f);
    spmm_kernel<<<SB, 256>>>(Qh, Q, P, P, nullptr, dt2, -1.0f, 2.0f);

    gather_kernel<<<(BB * RR * 32 + 255) / 256, 256>>>(P, BN, out);
}

// round 12
// speedup vs baseline: 2.6381x; 1.0134x over previous
#include <cuda_runtime.h>
#include <cuda_fp16.h>
#include <cstdint>

#define NN 50000
#define EE 800000
#define RR 3
#define FIN 256
#define CC 128
#define BB 4096
#define DTC 0.25f

#define RN (RR * NN)          // 150000 merged nodes
#define RE (RR * EE)          // 2400000 merged edges
#define GBK 391               // gemm row blocks (ceil(NN/128))

// ---------------- static scratch ----------------
__device__ __align__(16) float  g_P[(size_t)RN * CC];   // ping (fp32)
__device__ __align__(16) float  g_Q[(size_t)RN * CC];   // pong (fp32)
__device__ __align__(16) __half g_Ph[(size_t)RN * CC];  // fp16 shadow of P
__device__ __align__(16) __half g_Qh[(size_t)RN * CC];  // fp16 shadow of Q
__device__ int   g_cnt[RN];
__device__ int   g_ptr[RN + 1];
__device__ int   g_cur[RN];
__device__ float g_dinv[RN];
__device__ __align__(8) int2 g_edge[RE];  // {global src row, bitcast fp32 dinv[src]}
__device__ int   g_bsum[256];
__device__ int   g_boff[256];
// pre-swizzled fp16 operand images: [blk][slab][row][8 x 16B chunks]
__device__ __align__(16) uint4 g_Xh[(size_t)GBK * 4096];  // 391*4 slabs*1024 chunks
__device__ __align__(16) uint4 g_Wh[6 * 4096];            // 6 mats * 4 slabs * 1024

// ---------------- CSC build ----------------
__global__ void zero_kernel() {
    int i = blockIdx.x * blockDim.x + threadIdx.x;
    if (i < RN) g_cnt[i] = 0;
}

__global__ void hist_kernel(const int* __restrict__ EI) {
    int e = blockIdx.x * blockDim.x + threadIdx.x;
    int rel = blockIdx.y;
    if (e < EE) {
        int c = EI[(size_t)rel * 2 * EE + EE + e];
        atomicAdd(&g_cnt[rel * NN + c], 1);
    }
}

__global__ void __launch_bounds__(1024) scanA_kernel() {
    __shared__ int sh[1024];
    int t = threadIdx.x;
    int i = blockIdx.x * 1024 + t;
    int v = (i < RN) ? g_cnt[i] : 0;
    sh[t] = v;
    __syncthreads();
    #pragma unroll
    for (int off = 1; off < 1024; off <<= 1) {
        int add = (t >= off) ? sh[t - off] : 0;
        __syncthreads();
        sh[t] += add;
        __syncthreads();
    }
    if (i < RN) g_ptr[i] = sh[t] - v;
    if (t == 1023) g_bsum[blockIdx.x] = sh[t];
}

__global__ void __launch_bounds__(256) scanB_kernel(int nblocks) {
    __shared__ int sh[256];
    int t = threadIdx.x;
    int v = (t < nblocks) ? g_bsum[t] : 0;
    sh[t] = v;
    __syncthreads();
    #pragma unroll
    for (int off = 1; off < 256; off <<= 1) {
        int add = (t >= off) ? sh[t - off] : 0;
        __syncthreads();
        sh[t] += add;
        __syncthreads();
    }
    if (t < nblocks) g_boff[t] = sh[t] - v;
}

__global__ void scanC_kernel() {
    int i = blockIdx.x * blockDim.x + threadIdx.x;
    if (i < RN) {
        int p = g_ptr[i] + g_boff[i >> 10];
        g_ptr[i] = p;
        g_cur[i] = p;
        int c = g_cnt[i];
        g_dinv[i] = (c > 0) ? (1.0f / sqrtf((float)c)) : 0.0f;
    }
    if (i == 0) g_ptr[RN] = RE;
}

__global__ void scatter_kernel(const int* __restrict__ EI) {
    int e = blockIdx.x * blockDim.x + threadIdx.x;
    int rel = blockIdx.y;
    if (e < EE) {
        const int* base = EI + (size_t)rel * 2 * EE;
        int s = rel * NN + base[e];
        int c = base[EE + e];
        int p = atomicAdd(&g_cur[rel * NN + c], 1);
        g_edge[p] = make_int2(s, __float_as_int(g_dinv[s]));
    }
}

// ---------------- fp16 operand prep (convert + swizzle once) ----------------
__device__ __forceinline__ unsigned packh2(float a, float b) {
    __half2 h = __floats2half2_rn(a, b);
    return *(unsigned*)&h;
}

// one thread per 16B output chunk. chunk image: row*8 + (chunk ^ (row&7))
__global__ void prepx_kernel(const float* __restrict__ X) {
    int t = blockIdx.x * blockDim.x + threadIdx.x;
    if (t >= GBK * 4096) return;
    int chunk = t & 7;
    int row   = (t >> 3) & 127;
    int slab  = (t >> 10) & 3;
    int blk   = t >> 12;
    int grow  = blk * 128 + row;
    uint4 o = make_uint4(0u, 0u, 0u, 0u);
    if (grow < NN) {
        const float* src = X + (size_t)grow * FIN + slab * 64 + chunk * 8;
        float4 f0 = *(const float4*)src;
        float4 f1 = *(const float4*)(src + 4);
        o.x = packh2(f0.x, f0.y); o.y = packh2(f0.z, f0.w);
        o.z = packh2(f1.x, f1.y); o.w = packh2(f1.z, f1.w);
    }
    int cs = chunk ^ (row & 7);
    g_Xh[(size_t)((blk * 4 + slab) * 128 + row) * 8 + cs] = o;
}

__global__ void prepw_kernel(const float* __restrict__ W0,
                             const float* __restrict__ W1) {
    int t = blockIdx.x * blockDim.x + threadIdx.x;
    if (t >= 6 * 4096) return;
    int chunk = t & 7;
    int row   = (t >> 3) & 127;
    int slab  = (t >> 10) & 3;
    int mat   = t >> 12;             // = blockIdx.y of gemm
    int rel = mat >> 1, which = mat & 1;
    const float* W = (which ? W1 : W0) + (size_t)rel * CC * FIN;
    const float* src = W + (size_t)row * FIN + slab * 64 + chunk * 8;
    float4 f0 = *(const float4*)src;
    float4 f1 = *(const float4*)(src + 4);
    uint4 o;
    o.x = packh2(f0.x, f0.y); o.y = packh2(f0.z, f0.w);
    o.z = packh2(f1.x, f1.y); o.w = packh2(f1.z, f1.w);
    int cs = chunk ^ (row & 7);
    g_Wh[((mat * 4 + slab) * 128 + row) * 8 + cs] = o;
}

// ---------------- fp16 MMA GEMM with cp.async double buffering ----------------
// dynamic smem: [bufA0 16KB][bufA1 16KB][bufB0 16KB][bufB1 16KB] = 64KB
__global__ void __launch_bounds__(256) gemm_kernel(const float* __restrict__ B0,
                                                   const float* __restrict__ B1) {
    extern __shared__ __align__(16) char dsmem[];
    int rel   = blockIdx.y >> 1;
    int which = blockIdx.y & 1;
    const float* Bv = (which ? B1 : B0) + (size_t)rel * CC;
    float* out = (which ? g_Q : g_P) + (size_t)rel * NN * CC;

    const uint4* Xs = g_Xh + (size_t)blockIdx.x * 4096;
    const uint4* Ws = g_Wh + (size_t)blockIdx.y * 4096;

    int tid  = threadIdx.x;
    int lane = tid & 31;
    int wid  = tid >> 5;
    int m0w  = (wid >> 1) * 32;
    int n0w  = (wid & 1) * 64;
    int rowBase = blockIdx.x * 128;

    unsigned dynu = (unsigned)__cvta_generic_to_shared(dsmem);

    float d[2][8][4];
    #pragma unroll
    for (int mt = 0; mt < 2; mt++)
        #pragma unroll
        for (int nt = 0; nt < 8; nt++)
            #pragma unroll
            for (int i = 0; i < 4; i++) d[mt][nt][i] = 0.0f;

    auto prefetch = [&](int s, int buf) {
        const uint4* srcA = Xs + s * 1024 + tid;
        const uint4* srcB = Ws + s * 1024 + tid;
        unsigned dA = dynu + buf * 16384 + tid * 16;
        unsigned dB = dynu + 32768 + buf * 16384 + tid * 16;
        #pragma unroll
        for (int j = 0; j < 4; j++) {
            asm volatile("cp.async.cg.shared.global [%0], [%1], 16;"
                         :: "r"(dA + j * 4096), "l"(srcA + j * 256));
            asm volatile("cp.async.cg.shared.global [%0], [%1], 16;"
                         :: "r"(dB + j * 4096), "l"(srcB + j * 256));
        }
    };

    prefetch(0, 0);
    asm volatile("cp.async.commit_group;");

    #pragma unroll
    for (int s = 0; s < 4; s++) {
        if (s < 3) {
            prefetch(s + 1, (s + 1) & 1);
            asm volatile("cp.async.commit_group;");
            asm volatile("cp.async.wait_group 1;");
        } else {
            asm volatile("cp.async.wait_group 0;");
        }
        __syncthreads();

        unsigned sAu = dynu + (s & 1) * 16384;
        unsigned sBu = dynu + 32768 + (s & 1) * 16384;

        #pragma unroll
        for (int kc = 0; kc < 4; kc++) {
            unsigned a0[4], a1[4];
            {
                int row = m0w + (lane & 15);
                int c   = kc * 2 + (lane >> 4);
                int cs  = c ^ (row & 7);
                unsigned addr = sAu + (unsigned)(row * 128 + cs * 16);
                asm volatile("ldmatrix.sync.aligned.m8n8.x4.shared.b16 {%0,%1,%2,%3}, [%4];"
                    : "=r"(a0[0]), "=r"(a0[1]), "=r"(a0[2]), "=r"(a0[3])
                    : "r"(addr));
            }
            {
                int row = m0w + 16 + (lane & 15);
                int c   = kc * 2 + (lane >> 4);
                int cs  = c ^ (row & 7);
                unsigned addr = sAu + (unsigned)(row * 128 + cs * 16);
                asm volatile("ldmatrix.sync.aligned.m8n8.x4.shared.b16 {%0,%1,%2,%3}, [%4];"
                    : "=r"(a1[0]), "=r"(a1[1]), "=r"(a1[2]), "=r"(a1[3])
                    : "r"(addr));
            }
            #pragma unroll
            for (int np = 0; np < 4; np++) {
                int quad = lane >> 3;
                int row  = n0w + np * 16 + (quad >> 1) * 8 + (lane & 7);
                int c    = kc * 2 + (quad & 1);
                int cs   = c ^ (row & 7);
                unsigned addr = sBu + (unsigned)(row * 128 + cs * 16);
                unsigned b0, b1, b2, b3;
                asm volatile("ldmatrix.sync.aligned.m8n8.x4.shared.b16 {%0,%1,%2,%3}, [%4];"
                    : "=r"(b0), "=r"(b1), "=r"(b2), "=r"(b3) : "r"(addr));
                asm volatile(
                    "mma.sync.aligned.m16n8k16.row.col.f32.f16.f16.f32 "
                    "{%0,%1,%2,%3}, {%4,%5,%6,%7}, {%8,%9}, {%0,%1,%2,%3};"
                    : "+f"(d[0][2*np][0]), "+f"(d[0][2*np][1]),
                      "+f"(d[0][2*np][2]), "+f"(d[0][2*np][3])
                    : "r"(a0[0]), "r"(a0[1]), "r"(a0[2]), "r"(a0[3]),
                      "r"(b0), "r"(b1));
                asm volatile(
                    "mma.sync.aligned.m16n8k16.row.col.f32.f16.f16.f32 "
                    "{%0,%1,%2,%3}, {%4,%5,%6,%7}, {%8,%9}, {%0,%1,%2,%3};"
                    : "+f"(d[0][2*np+1][0]), "+f"(d[0][2*np+1][1]),
                      "+f"(d[0][2*np+1][2]), "+f"(d[0][2*np+1][3])
                    : "r"(a0[0]), "r"(a0[1]), "r"(a0[2]), "r"(a0[3]),
                      "r"(b2), "r"(b3));
                asm volatile(
                    "mma.sync.aligned.m16n8k16.row.col.f32.f16.f16.f32 "
                    "{%0,%1,%2,%3}, {%4,%5,%6,%7}, {%8,%9}, {%0,%1,%2,%3};"
                    : "+f"(d[1][2*np][0]), "+f"(d[1][2*np][1]),
                      "+f"(d[1][2*np][2]), "+f"(d[1][2*np][3])
                    : "r"(a1[0]), "r"(a1[1]), "r"(a1[2]), "r"(a1[3]),
                      "r"(b0), "r"(b1));
                asm volatile(
                    "mma.sync.aligned.m16n8k16.row.col.f32.f16.f16.f32 "
                    "{%0,%1,%2,%3}, {%4,%5,%6,%7}, {%8,%9}, {%0,%1,%2,%3};"
                    : "+f"(d[1][2*np+1][0]), "+f"(d[1][2*np+1][1]),
                      "+f"(d[1][2*np+1][2]), "+f"(d[1][2*np+1][3])
                    : "r"(a1[0]), "r"(a1[1]), "r"(a1[2]), "r"(a1[3]),
                      "r"(b2), "r"(b3));
            }
        }
        __syncthreads();
    }

    // epilogue
    int gid = lane >> 2, tig = lane & 3;
    #pragma unroll
    for (int mt = 0; mt < 2; mt++) {
        int r0 = rowBase + m0w + mt * 16 + gid;
        int r1 = r0 + 8;
        #pragma unroll
        for (int nt = 0; nt < 8; nt++) {
            int cidx = n0w + nt * 8 + tig * 2;
            float bx = Bv[cidx], by = Bv[cidx + 1];
            if (r0 < NN)
                *(float2*)(out + (size_t)r0 * CC + cidx) =
                    make_float2(d[mt][nt][0] + bx, d[mt][nt][1] + by);
            if (r1 < NN)
                *(float2*)(out + (size_t)r1 * CC + cidx) =
                    make_float2(d[mt][nt][2] + bx, d[mt][nt][3] + by);
        }
    }
}

// ---------------- coalesced fp32 -> fp16 shadow convert (P -> Ph) ----------------
__global__ void p2h_kernel() {
    size_t i = (size_t)blockIdx.x * blockDim.x + threadIdx.x;
    if (i >= (size_t)RN * CC / 8) return;
    const float4* src = (const float4*)g_P;
    float4 a = src[i * 2];
    float4 b = src[i * 2 + 1];
    uint4 h;
    h.x = packh2(a.x, a.y); h.y = packh2(a.z, a.w);
    h.z = packh2(b.x, b.y); h.w = packh2(b.z, b.w);
    ((uint4*)g_Ph)[i] = h;
}

// ---------------- fused SpMM + wave update ----------------
// fp32 streams evict-first (__ldcs/__stcs) so the fp16 gather sources stay in L2.
__global__ void __launch_bounds__(256) spmm_kernel(const __half* __restrict__ xgh,
                                                   const float*  __restrict__ xg,
                                                   const float*  __restrict__ xa,
                                                   float*  __restrict__ out,
                                                   __half* __restrict__ outh,
                                                   float cg, float ca, float cb) {
    int w    = (blockIdx.x * blockDim.x + threadIdx.x) >> 5;  // global dst row
    int lane = threadIdx.x & 31;
    if (w >= RN) return;
    int p0 = g_ptr[w], p1 = g_ptr[w + 1];
    int hw = lane >> 4;                   // half-warp id
    int hl = lane & 15;                   // 16 lanes x 8 fp16 channels

    float acc[8];
    #pragma unroll
    for (int i = 0; i < 8; i++) acc[i] = 0.0f;

    int k = p0 + 2 * hw;
    for (; k + 1 < p1; k += 4) {
        int2 e0 = __ldg(&g_edge[k]);
        int2 e1 = __ldg(&g_edge[k + 1]);
        uint4 h0 = *(const uint4*)(xgh + (size_t)e0.x * CC + hl * 8);
        uint4 h1 = *(const uint4*)(xgh + (size_t)e1.x * CC + hl * 8);
        float w0 = __int_as_float(e0.y);
        float w1 = __int_as_float(e1.y);
        float2 f;
        f = __half22float2(*(__half2*)&h0.x); acc[0] += w0 * f.x; acc[1] += w0 * f.y;
        f = __half22float2(*(__half2*)&h0.y); acc[2] += w0 * f.x; acc[3] += w0 * f.y;
        f = __half22float2(*(__half2*)&h0.z); acc[4] += w0 * f.x; acc[5] += w0 * f.y;
        f = __half22float2(*(__half2*)&h0.w); acc[6] += w0 * f.x; acc[7] += w0 * f.y;
        f = __half22float2(*(__half2*)&h1.x); acc[0] += w1 * f.x; acc[1] += w1 * f.y;
        f = __half22float2(*(__half2*)&h1.y); acc[2] += w1 * f.x; acc[3] += w1 * f.y;
        f = __half22float2(*(__half2*)&h1.z); acc[4] += w1 * f.x; acc[5] += w1 * f.y;
        f = __half22float2(*(__half2*)&h1.w); acc[6] += w1 * f.x; acc[7] += w1 * f.y;
    }
    if (k < p1) {
        int2 e0 = __ldg(&g_edge[k]);
        uint4 h0 = *(const uint4*)(xgh + (size_t)e0.x * CC + hl * 8);
        float w0 = __int_as_float(e0.y);
        float2 f;
        f = __half22float2(*(__half2*)&h0.x); acc[0] += w0 * f.x; acc[1] += w0 * f.y;
        f = __half22float2(*(__half2*)&h0.y); acc[2] += w0 * f.x; acc[3] += w0 * f.y;
        f = __half22float2(*(__half2*)&h0.z); acc[4] += w0 * f.x; acc[5] += w0 * f.y;
        f = __half22float2(*(__half2*)&h0.w); acc[6] += w0 * f.x; acc[7] += w0 * f.y;
    }

    #pragma unroll
    for (int i = 0; i < 8; i++) acc[i] += __shfl_down_sync(0xffffffffu, acc[i], 16);
    float v[4];
    #pragma unroll
    for (int j = 0; j < 4; j++) {
        float t0 = __shfl_sync(0xffffffffu, acc[j],     lane >> 1);
        float t1 = __shfl_sync(0xffffffffu, acc[4 + j], lane >> 1);
        v[j] = (lane & 1) ? t1 : t0;
    }

    float cgd = cg * g_dinv[w];
    size_t o = (size_t)w * CC + lane * 4;
    float4 av = __ldcs((const float4*)(xa + o));   // streaming: no L2 stickiness
    float4 gv = __ldcs((const float4*)(xg + o));
    float4 r;
    r.x = cgd * v[0] + ca * av.x + cb * gv.x;
    r.y = cgd * v[1] + ca * av.y + cb * gv.y;
    r.z = cgd * v[2] + ca * av.z + cb * gv.z;
    r.w = cgd * v[3] + ca * av.w + cb * gv.w;
    __stcs((float4*)(out + o), r);                 // streaming store
    if (outh) {
        uint2 hv;
        hv.x = packh2(r.x, r.y);
        hv.y = packh2(r.z, r.w);
        *(uint2*)(outh + o) = hv;                  // cache-normal: next step's gather source
    }
}

// ---------------- final gather ----------------
__global__ void gather_kernel(const float* __restrict__ x,
                              const int* __restrict__ bn,
                              float* __restrict__ out) {
    int t = blockIdx.x * blockDim.x + threadIdx.x;
    if (t >= BB * RR * 32) return;
    int q = t & 31;
    int r = (t >> 5) % RR;
    int b = t / (32 * RR);
    int node = bn[b];
    ((float4*)out)[(size_t)b * (RR * CC / 4) + r * (CC / 4) + q] =
        ((const float4*)x)[((size_t)r * NN + node) * (CC / 4) + q];
}

// ---------------- driver ----------------
extern "C" void kernel_launch(void* const* d_in, const int* in_sizes, int n_in,
                              void* d_out, int out_size) {
    const float* X  = (const float*)d_in[0];
    const int*   EI = (const int*)d_in[1];
    const int*   BN = (const int*)d_in[2];
    const float* W0 = (const float*)d_in[3];
    const float* B0 = (const float*)d_in[4];
    const float* W1 = (const float*)d_in[5];
    const float* B1 = (const float*)d_in[6];
    float* out = (float*)d_out;

    float *P, *Q;
    __half *Ph, *Qh;
    cudaGetSymbolAddress((void**)&P, g_P);
    cudaGetSymbolAddress((void**)&Q, g_Q);
    cudaGetSymbolAddress((void**)&Ph, g_Ph);
    cudaGetSymbolAddress((void**)&Qh, g_Qh);

    cudaFuncSetAttribute(gemm_kernel,
                         cudaFuncAttributeMaxDynamicSharedMemorySize, 65536);

    const int EB  = (EE + 255) / 256;
    const int ZB  = (RN + 255) / 256;
    const int SCB = (RN + 1023) / 1024;
    const int SB  = (RN * 32 + 255) / 256;
    const int PB  = ((RN * CC / 8) + 255) / 256;
    const int PXB = (GBK * 4096 + 255) / 256;

    const float dt2  = DTC * DTC;
    const float dt2h = 0.5f * dt2;

    zero_kernel<<<ZB, 256>>>();
    hist_kernel<<<dim3(EB, RR), 256>>>(EI);
    prepx_kernel<<<PXB, 256>>>(X);
    prepw_kernel<<<(6 * 4096 + 255) / 256, 256>>>(W0, W1);
    scanA_kernel<<<SCB, 1024>>>();
    gemm_kernel<<<dim3(GBK, 2 * RR), 256, 65536>>>(B0, B1);   // phi0->P, phi1->Q
    scanB_kernel<<<1, 256>>>(SCB);
    scanC_kernel<<<ZB, 256>>>();
    scatter_kernel<<<dim3(EB, RR), 256>>>(EI);
    p2h_kernel<<<PB, 256>>>();                                // P -> Ph

    // x1 = dt*phi1 + (dt^2/2)*Ahat phi0 + phi0
    spmm_kernel<<<SB, 256>>>(Ph, P, Q, Q, Qh, dt2h, DTC, 1.0f);
    // xn = dt^2*Ahat xc + 2 xc - xp
    spmm_kernel<<<SB, 256>>>(Qh, Q, P, P, Ph, dt2, -1.0f, 2.0f);
    spmm_kernel<<<SB, 256>>>(Ph, P, Q, Q, Qh, dt2, -1.0f, 2.0f);
    spmm_kernel<<<SB, 256>>>(Qh, Q, P, P, nullptr, dt2, -1.0f, 2.0f);

    gather_kernel<<<(BB * RR * 32 + 255) / 256, 256>>>(P, BN, out);
}